// round 2
// baseline (speedup 1.0000x reference)
#include <cuda_runtime.h>
#include <cstdint>
#include <cstddef>

// ---------------------------------------------------------------------------
// Static problem geometry (LENGTHS are compile-time constants in the reference)
// ---------------------------------------------------------------------------
#define NGRAPH   16
#define NNODES   4033
#define RREL     4
#define NHEAD    8
#define FIN      256
#define RN       16132
#define NWIN     132
#define PROJ     1024

__constant__ int c_CUML[NGRAPH]   = {0,251,498,761,1016,1256,1514,1763,2023,2275,2520,2776,3026,3274,3535,3779};
__constant__ int c_LEN[NGRAPH]    = {251,247,263,255,240,258,249,260,252,245,256,250,248,261,244,254};
__constant__ int c_CUMNW[NGRAPH+1]= {0,8,16,25,33,41,50,58,67,75,83,91,99,107,116,124,132};

// scratch: fused Q|K projections, row m = rr*NNODES + node, cols [0,512)=Q, [512,1024)=K
__device__ float g_QK[(size_t)RN * PROJ];   // 66 MB

// ---------------------------------------------------------------------------
// Packed fp32 helpers (Blackwell f32x2 — 2 FMAs per issue slot, exact fp32)
// ---------------------------------------------------------------------------
__device__ __forceinline__ void ffma2(unsigned long long& d,
                                      unsigned long long a,
                                      unsigned long long b) {
    asm("fma.rn.f32x2 %0, %1, %2, %0;" : "+l"(d) : "l"(a), "l"(b));
}
__device__ __forceinline__ unsigned long long dup2(float x) {
    unsigned long long r;
    asm("mov.b64 %0, {%1, %1};" : "=l"(r) : "f"(x));
    return r;
}
__device__ __forceinline__ float lo32(unsigned long long v) { return __uint_as_float((unsigned)v); }
__device__ __forceinline__ float hi32(unsigned long long v) { return __uint_as_float((unsigned)(v >> 32)); }

// ---------------------------------------------------------------------------
// GEMM: C[RN,1024] = A[RN,256] * [Wq;Wk]^T + [bq;bk]    (f32x2 packed FMA)
// Block tile 128m x 128n, k-tile 8, 256 threads.
// Thread: rows ty*16..+15 (8 m-pairs), cols tx*4..+3. acc = 32 f32x2 pairs.
// B stored in smem DUPLICATED (b,b) with bank padding -> zero dup-MOV FFMA2.
// ---------------------------------------------------------------------------
__global__ __launch_bounds__(256, 2) void gemm_kernel(
    const float* __restrict__ A,
    const float* __restrict__ Wq, const float* __restrict__ bq,
    const float* __restrict__ Wk, const float* __restrict__ bk)
{
    __shared__ __align__(16) float As[8][128];   // k-major A tile
    __shared__ __align__(16) float Bs[8][384];   // dup'd B: groups of 8 words + 4 pad

    const int bn  = blockIdx.x;          // 0..7
    const int bm  = blockIdx.y;          // 0..126
    const int m0  = bm * 128;
    const int n0g = bn * 128;

    const float* B; const float* bias; int n0;
    if (n0g < 512) { B = Wq; bias = bq; n0 = n0g; }
    else           { B = Wk; bias = bk; n0 = n0g - 512; }

    const int tid = threadIdx.x;
    const int tx  = tid & 31;            // n
    const int ty  = tid >> 5;            // m

    const int lrow = tid >> 1;           // 0..127
    const int lcf  = (tid & 1) * 4;      // 0 or 4
    const int p2   = 2 * lrow + (lrow >> 2) * 4;   // padded dup word base

    unsigned long long acc[8][4];
#pragma unroll
    for (int p = 0; p < 8; p++)
#pragma unroll
        for (int j = 0; j < 4; j++) acc[p][j] = 0ull;

#pragma unroll 1
    for (int k0 = 0; k0 < FIN; k0 += 8) {
        float4 av = make_float4(0.f, 0.f, 0.f, 0.f);
        const int gm = m0 + lrow;
        if (gm < RN) av = *reinterpret_cast<const float4*>(A + (size_t)gm * FIN + k0 + lcf);
        float4 bv = *reinterpret_cast<const float4*>(B + (size_t)(n0 + lrow) * FIN + k0 + lcf);

        __syncthreads();
        As[lcf + 0][lrow] = av.x; As[lcf + 1][lrow] = av.y;
        As[lcf + 2][lrow] = av.z; As[lcf + 3][lrow] = av.w;
        *reinterpret_cast<unsigned long long*>(&Bs[lcf + 0][p2]) = dup2(bv.x);
        *reinterpret_cast<unsigned long long*>(&Bs[lcf + 1][p2]) = dup2(bv.y);
        *reinterpret_cast<unsigned long long*>(&Bs[lcf + 2][p2]) = dup2(bv.z);
        *reinterpret_cast<unsigned long long*>(&Bs[lcf + 3][p2]) = dup2(bv.w);
        __syncthreads();

#pragma unroll
        for (int kk = 0; kk < 8; kk++) {
            ulonglong2 a0 = *reinterpret_cast<const ulonglong2*>(&As[kk][ty * 16 + 0]);
            ulonglong2 a1 = *reinterpret_cast<const ulonglong2*>(&As[kk][ty * 16 + 4]);
            ulonglong2 a2 = *reinterpret_cast<const ulonglong2*>(&As[kk][ty * 16 + 8]);
            ulonglong2 a3 = *reinterpret_cast<const ulonglong2*>(&As[kk][ty * 16 + 12]);
            ulonglong2 b0 = *reinterpret_cast<const ulonglong2*>(&Bs[kk][tx * 12 + 0]);
            ulonglong2 b1 = *reinterpret_cast<const ulonglong2*>(&Bs[kk][tx * 12 + 4]);
            unsigned long long ap[8] = {a0.x, a0.y, a1.x, a1.y, a2.x, a2.y, a3.x, a3.y};
            unsigned long long bp[4] = {b0.x, b0.y, b1.x, b1.y};
#pragma unroll
            for (int p = 0; p < 8; p++)
#pragma unroll
                for (int j = 0; j < 4; j++)
                    ffma2(acc[p][j], ap[p], bp[j]);
        }
    }

    // epilogue: unpack pairs (rows 2p, 2p+1), add bias, vector stores
    const float4 bsv = *reinterpret_cast<const float4*>(&bias[n0 + tx * 4]);
#pragma unroll
    for (int p = 0; p < 8; p++) {
        const int r0 = m0 + ty * 16 + 2 * p;
        float4 v0, v1;
        v0.x = lo32(acc[p][0]) + bsv.x; v0.y = lo32(acc[p][1]) + bsv.y;
        v0.z = lo32(acc[p][2]) + bsv.z; v0.w = lo32(acc[p][3]) + bsv.w;
        v1.x = hi32(acc[p][0]) + bsv.x; v1.y = hi32(acc[p][1]) + bsv.y;
        v1.z = hi32(acc[p][2]) + bsv.z; v1.w = hi32(acc[p][3]) + bsv.w;
        if (r0 < RN)
            *reinterpret_cast<float4*>(&g_QK[(size_t)r0 * PROJ + n0g + tx * 4]) = v0;
        if (r0 + 1 < RN)
            *reinterpret_cast<float4*>(&g_QK[(size_t)(r0 + 1) * PROJ + n0g + tx * 4]) = v1;
    }
}

// ---------------------------------------------------------------------------
// Attention: block = (kept window, relation). 32 queries x 96 keys, 8 heads,
// softmax per head (NO max-subtraction: logits provably tiny; masked -> e=0),
// mean over heads, scatter into banded dense output.
// Double-buffered dynamic smem; vectorized LDS + packed f32x2 dot products.
// Warp w owns query rows 4w..4w+3; lane l owns keys {l, 32+l, 64+l}.
// ---------------------------------------------------------------------------
#define Q_ELEMS (32 * 68)
#define K_ELEMS (96 * 68)
#define ATTN_SMEM ((2 * Q_ELEMS + 2 * K_ELEMS) * (int)sizeof(float))

__global__ __launch_bounds__(256, 3) void attn_kernel(float* __restrict__ out)
{
    extern __shared__ __align__(16) float sm[];
    // layout: Q buf0 | Q buf1 | K buf0 | K buf1   (stride-68 rows: conflict-free)
    float* Qb[2] = { sm,              sm + Q_ELEMS };
    float* Kb[2] = { sm + 2 * Q_ELEMS, sm + 2 * Q_ELEMS + K_ELEMS };

    __shared__ int qn[32];
    __shared__ int kn[96];

    const int wi  = blockIdx.x;
    const int rr  = blockIdx.y;
    const int tid = threadIdx.x;

    int g = 0;
#pragma unroll
    for (int t = 1; t < NGRAPH; t++) g += (c_CUMNW[t] <= wi);
    const int pofs = (wi - c_CUMNW[g]) * 32;   // window start within graph

    if (tid < 32) {
        const int k = pofs + tid;
        qn[tid] = (k < c_LEN[g]) ? c_CUML[g] + k : -1;
    } else if (tid < 128) {
        const int c = tid - 32;
        const int k = pofs - 32 + c;
        kn[c] = (k >= 0 && k < c_LEN[g]) ? c_CUML[g] + k : -1;
    }
    __syncthreads();

    const int warp = tid >> 5;
    const int lane = tid & 31;
    const bool v0 = kn[lane] >= 0, v1 = kn[32 + lane] >= 0, v2 = kn[64 + lane] >= 0;

    const float* Qbase = g_QK + (size_t)rr * NNODES * PROJ;

    // cooperative head loader (float4, coalesced; skips padding nodes —
    // stale smem is provably masked out downstream)
    auto load_head = [&](int h, int b) {
#pragma unroll
        for (int it = 0; it < 2; it++) {
            const int i = tid + it * 256;
            const int s = i >> 4, d4 = (i & 15) << 2;
            const int node = qn[s];
            if (node >= 0)
                *reinterpret_cast<float4*>(&Qb[b][s * 68 + d4]) =
                    *reinterpret_cast<const float4*>(&Qbase[(size_t)node * PROJ + h * 64 + d4]);
        }
#pragma unroll
        for (int it = 0; it < 6; it++) {
            const int i = tid + it * 256;
            const int c = i >> 4, d4 = (i & 15) << 2;
            const int node = kn[c];
            if (node >= 0)
                *reinterpret_cast<float4*>(&Kb[b][c * 68 + d4]) =
                    *reinterpret_cast<const float4*>(&Qbase[(size_t)node * PROJ + 512 + h * 64 + d4]);
        }
    };

    float acc[4][3];
#pragma unroll
    for (int i = 0; i < 4; i++)
#pragma unroll
        for (int j = 0; j < 3; j++) acc[i][j] = 0.f;

    load_head(0, 0);

#pragma unroll 1
    for (int h = 0; h < NHEAD; h++) {
        const int b = h & 1;
        __syncthreads();                     // drains pending STS for buf b
        if (h + 1 < NHEAD) load_head(h + 1, b ^ 1);

        unsigned long long lg[4][3];
#pragma unroll
        for (int i = 0; i < 4; i++)
#pragma unroll
            for (int j = 0; j < 3; j++) lg[i][j] = 0ull;

        const float* kr0 = &Kb[b][lane * 68];
        const float* kr1 = &Kb[b][(32 + lane) * 68];
        const float* kr2 = &Kb[b][(64 + lane) * 68];
        const float* qr  = &Qb[b][(warp * 4) * 68];

#pragma unroll
        for (int c = 0; c < 16; c++) {
            const ulonglong2 k0 = *reinterpret_cast<const ulonglong2*>(kr0 + c * 4);
            const ulonglong2 k1 = *reinterpret_cast<const ulonglong2*>(kr1 + c * 4);
            const ulonglong2 k2 = *reinterpret_cast<const ulonglong2*>(kr2 + c * 4);
#pragma unroll
            for (int qi = 0; qi < 4; qi++) {
                const ulonglong2 q = *reinterpret_cast<const ulonglong2*>(qr + qi * 68 + c * 4);
                ffma2(lg[qi][0], q.x, k0.x); ffma2(lg[qi][0], q.y, k0.y);
                ffma2(lg[qi][1], q.x, k1.x); ffma2(lg[qi][1], q.y, k1.y);
                ffma2(lg[qi][2], q.x, k2.x); ffma2(lg[qi][2], q.y, k2.y);
            }
        }

#pragma unroll
        for (int qi = 0; qi < 4; qi++) {
            // logits are O(1): exp cannot overflow -> no max-subtraction needed
            const float e0 = v0 ? __expf((lo32(lg[qi][0]) + hi32(lg[qi][0])) * 0.125f) : 0.f;
            const float e1 = v1 ? __expf((lo32(lg[qi][1]) + hi32(lg[qi][1])) * 0.125f) : 0.f;
            const float e2 = v2 ? __expf((lo32(lg[qi][2]) + hi32(lg[qi][2])) * 0.125f) : 0.f;
            float s = e0 + e1 + e2;
#pragma unroll
            for (int off = 16; off > 0; off >>= 1)
                s += __shfl_xor_sync(0xffffffffu, s, off);
            const float inv = __fdividef(1.f, s);
            acc[qi][0] += e0 * inv;
            acc[qi][1] += e1 * inv;
            acc[qi][2] += e2 * inv;
        }
    }

    // scatter: out[q, rr*NNODES + k] = mean over heads
#pragma unroll
    for (int qi = 0; qi < 4; qi++) {
        const int q = qn[warp * 4 + qi];
        if (q < 0) continue;
        const size_t rowbase = (size_t)q * RN + (size_t)rr * NNODES;
        if (v0) out[rowbase + kn[lane]]      = acc[qi][0] * 0.125f;
        if (v1) out[rowbase + kn[32 + lane]] = acc[qi][1] * 0.125f;
        if (v2) out[rowbase + kn[64 + lane]] = acc[qi][2] * 0.125f;
    }
}

// ---------------------------------------------------------------------------
extern "C" void kernel_launch(void* const* d_in, const int* in_sizes, int n_in,
                              void* d_out, int out_size)
{
    const float* nf = (const float*)d_in[0];
    const float* Wq = (const float*)d_in[1];
    const float* bq = (const float*)d_in[2];
    const float* Wk = (const float*)d_in[3];
    const float* bk = (const float*)d_in[4];
    float* out = (float*)d_out;

    cudaFuncSetAttribute(attn_kernel, cudaFuncAttributeMaxDynamicSharedMemorySize, ATTN_SMEM);

    cudaMemsetAsync(out, 0, (size_t)out_size * sizeof(float));

    dim3 ggrid(8, (RN + 127) / 128);
    gemm_kernel<<<ggrid, 256>>>(nf, Wq, bq, Wk, bk);

    dim3 agrid(NWIN, RREL);
    attn_kernel<<<agrid, 256, ATTN_SMEM>>>(out);
}

// round 3
// speedup vs baseline: 1.1643x; 1.1643x over previous
#include <cuda_runtime.h>
#include <cstdint>
#include <cstddef>

// ---------------------------------------------------------------------------
// Static problem geometry (LENGTHS are compile-time constants in the reference)
// ---------------------------------------------------------------------------
#define NGRAPH   16
#define NNODES   4033
#define RREL     4
#define NHEAD    8
#define FIN      256
#define RN       16132
#define NWIN     132
#define PROJ     1024

__constant__ int c_CUML[NGRAPH]   = {0,251,498,761,1016,1256,1514,1763,2023,2275,2520,2776,3026,3274,3535,3779};
__constant__ int c_LEN[NGRAPH]    = {251,247,263,255,240,258,249,260,252,245,256,250,248,261,244,254};
__constant__ int c_CUMNW[NGRAPH+1]= {0,8,16,25,33,41,50,58,67,75,83,91,99,107,116,124,132};

// scratch: fused Q|K projections, row m = rr*NNODES + node, cols [0,512)=Q, [512,1024)=K
__device__ float g_QK[(size_t)RN * PROJ];   // 66 MB

// ---------------------------------------------------------------------------
// tf32 split-precision helpers
// ---------------------------------------------------------------------------
__device__ __forceinline__ unsigned cvt_tf32(float x) {
    unsigned r;
    asm("cvt.rna.tf32.f32 %0, %1;" : "=r"(r) : "f"(x));
    return r;
}
__device__ __forceinline__ void split_tf32(float x, unsigned& hi, unsigned& lo) {
    hi = cvt_tf32(x);
    lo = cvt_tf32(x - __uint_as_float(hi));
}
__device__ __forceinline__ void mma_tf32(float* c, const unsigned* a,
                                         unsigned b0, unsigned b1) {
    asm volatile(
        "mma.sync.aligned.m16n8k8.row.col.f32.tf32.tf32.f32 "
        "{%0,%1,%2,%3}, {%4,%5,%6,%7}, {%8,%9}, {%0,%1,%2,%3};"
        : "+f"(c[0]), "+f"(c[1]), "+f"(c[2]), "+f"(c[3])
        : "r"(a[0]), "r"(a[1]), "r"(a[2]), "r"(a[3]), "r"(b0), "r"(b1));
}

// ---------------------------------------------------------------------------
// GEMM: C[RN,1024] = A[RN,256] * [Wq;Wk]^T + [bq;bk]
// tf32 tensor-core MMA with 3-pass fp32 split (error ~2^-22, effectively fp32).
// Block tile 128m x 128n, kc=32, 256 threads (8 warps: 4m x 2n, warp 32x64).
// ---------------------------------------------------------------------------
#define KC 32

__global__ __launch_bounds__(256) void gemm_kernel(
    const float* __restrict__ A,
    const float* __restrict__ Wq, const float* __restrict__ bq,
    const float* __restrict__ Wk, const float* __restrict__ bk)
{
    __shared__ float As[128][KC + 1];
    __shared__ float Bs[128][KC + 1];

    const int bn  = blockIdx.x;          // 0..7
    const int bm  = blockIdx.y;          // 0..126
    const int m0  = bm * 128;
    const int n0g = bn * 128;

    const float* B; const float* bias; int n0;
    if (n0g < 512) { B = Wq; bias = bq; n0 = n0g; }
    else           { B = Wk; bias = bk; n0 = n0g - 512; }

    const int tid  = threadIdx.x;
    const int warp = tid >> 5;
    const int lane = tid & 31;
    const int wm   = warp >> 1;          // 0..3 (32-row slice)
    const int wn   = warp & 1;           // 0..1 (64-col slice)
    const int grp  = lane >> 2;          // 0..7
    const int tig  = lane & 3;           // 0..3

    float acc[2][8][4];
#pragma unroll
    for (int mt = 0; mt < 2; mt++)
#pragma unroll
        for (int nt = 0; nt < 8; nt++)
#pragma unroll
            for (int i = 0; i < 4; i++) acc[mt][nt][i] = 0.f;

#pragma unroll 1
    for (int k0 = 0; k0 < FIN; k0 += KC) {
        // cooperative tile loads: 128 rows x 32 cols each, float4
#pragma unroll
        for (int it = 0; it < 4; it++) {
            const int idx = tid + it * 256;
            const int row = idx >> 3;
            const int c4  = (idx & 7) << 2;
            int gm = m0 + row; if (gm >= RN) gm = RN - 1;   // clamp (dup rows ok)
            const float4 av = *reinterpret_cast<const float4*>(A + (size_t)gm * FIN + k0 + c4);
            As[row][c4 + 0] = av.x; As[row][c4 + 1] = av.y;
            As[row][c4 + 2] = av.z; As[row][c4 + 3] = av.w;
            const float4 bv = *reinterpret_cast<const float4*>(B + (size_t)(n0 + row) * FIN + k0 + c4);
            Bs[row][c4 + 0] = bv.x; Bs[row][c4 + 1] = bv.y;
            Bs[row][c4 + 2] = bv.z; Bs[row][c4 + 3] = bv.w;
        }
        __syncthreads();

#pragma unroll
        for (int kk = 0; kk < KC; kk += 8) {
            // A fragments (hi/lo) for both 16-row m-tiles
            unsigned ah[2][4], al[2][4];
#pragma unroll
            for (int mt = 0; mt < 2; mt++) {
                const int r = wm * 32 + mt * 16 + grp;
                split_tf32(As[r    ][kk + tig    ], ah[mt][0], al[mt][0]);
                split_tf32(As[r + 8][kk + tig    ], ah[mt][1], al[mt][1]);
                split_tf32(As[r    ][kk + tig + 4], ah[mt][2], al[mt][2]);
                split_tf32(As[r + 8][kk + tig + 4], ah[mt][3], al[mt][3]);
            }
#pragma unroll
            for (int nt = 0; nt < 8; nt++) {
                const int nrow = wn * 64 + nt * 8 + grp;
                unsigned bh0, bl0, bh1, bl1;
                split_tf32(Bs[nrow][kk + tig    ], bh0, bl0);
                split_tf32(Bs[nrow][kk + tig + 4], bh1, bl1);
#pragma unroll
                for (int mt = 0; mt < 2; mt++) {
                    mma_tf32(acc[mt][nt], ah[mt], bh0, bh1);   // Ah*Bh
                    mma_tf32(acc[mt][nt], ah[mt], bl0, bl1);   // Ah*Bl
                    mma_tf32(acc[mt][nt], al[mt], bh0, bh1);   // Al*Bh
                }
            }
        }
        __syncthreads();
    }

    // epilogue: add bias, paired 64-bit stores
#pragma unroll
    for (int nt = 0; nt < 8; nt++) {
        const int cl = wn * 64 + nt * 8 + 2 * tig;      // local col
        const float bx = bias[n0 + cl];
        const float by = bias[n0 + cl + 1];
#pragma unroll
        for (int mt = 0; mt < 2; mt++) {
            const int r0 = m0 + wm * 32 + mt * 16 + grp;
            if (r0 < RN) {
                float2 v = make_float2(acc[mt][nt][0] + bx, acc[mt][nt][1] + by);
                *reinterpret_cast<float2*>(&g_QK[(size_t)r0 * PROJ + n0g + cl]) = v;
            }
            if (r0 + 8 < RN) {
                float2 v = make_float2(acc[mt][nt][2] + bx, acc[mt][nt][3] + by);
                *reinterpret_cast<float2*>(&g_QK[(size_t)(r0 + 8) * PROJ + n0g + cl]) = v;
            }
        }
    }
}

// ---------------------------------------------------------------------------
// Attention (round-1 structure): block = (kept window, relation).
// 32 queries x 96 keys, softmax per head (no max-sub: logits are O(0.1)),
// mean over 8 heads, FUSED output zeroing (block owns disjoint out region),
// scatter into banded dense output.
// Warp w owns query rows 4w..4w+3; lane l owns keys {l, 32+l, 64+l}.
// ---------------------------------------------------------------------------
__global__ __launch_bounds__(256) void attn_kernel(float* __restrict__ out)
{
    __shared__ float Qs[32][64];
    __shared__ float Kt[64][97];
    __shared__ int   qn[32];
    __shared__ int   kn[96];

    const int wi  = blockIdx.x;
    const int rr  = blockIdx.y;
    const int tid = threadIdx.x;

    int g = 0;
#pragma unroll
    for (int t = 1; t < NGRAPH; t++) g += (c_CUMNW[t] <= wi);
    const int pofs = (wi - c_CUMNW[g]) * 32;

    if (tid < 32) {
        const int k = pofs + tid;
        qn[tid] = (k < c_LEN[g]) ? c_CUML[g] + k : -1;
    } else if (tid < 128) {
        const int c = tid - 32;
        const int k = pofs - 32 + c;
        kn[c] = (k >= 0 && k < c_LEN[g]) ? c_CUML[g] + k : -1;
    }
    __syncthreads();

    const int warp = tid >> 5;
    const int lane = tid & 31;

    // ---- fused zeroing: warp w zeroes the 4 output rows it will scatter to,
    // over this relation's column slice [rr*NNODES, (rr+1)*NNODES) ----
    {
        const float4 z4 = make_float4(0.f, 0.f, 0.f, 0.f);
#pragma unroll
        for (int qi = 0; qi < 4; qi++) {
            const int q = qn[warp * 4 + qi];
            if (q < 0) continue;
            const size_t base = (size_t)q * RN + (size_t)rr * NNODES;
            const int head = (4 - (int)(base & 3)) & 3;      // floats to 16B align
            if (lane < head) out[base + lane] = 0.f;
            const size_t b4 = base + head;
            const int n4 = (NNODES - head) >> 2;
            for (int i = lane; i < n4; i += 32)
                *reinterpret_cast<float4*>(out + b4 + 4 * (size_t)i) = z4;
            const int done = head + (n4 << 2);
            if (done + lane < NNODES) out[base + done + lane] = 0.f;
        }
    }

    float acc[4][3];
#pragma unroll
    for (int i = 0; i < 4; i++)
#pragma unroll
        for (int j = 0; j < 3; j++) acc[i][j] = 0.f;

    const float* Qbase = g_QK + (size_t)rr * NNODES * PROJ;

    const int kidx0 = lane, kidx1 = 32 + lane, kidx2 = 64 + lane;
    const bool v0 = kn[kidx0] >= 0, v1 = kn[kidx1] >= 0, v2 = kn[kidx2] >= 0;

    for (int h = 0; h < NHEAD; h++) {
        for (int i = tid; i < 32 * 64; i += 256) {
            const int s = i >> 6, d = i & 63;
            const int node = qn[s];
            Qs[s][d] = (node >= 0) ? Qbase[(size_t)node * PROJ + h * 64 + d] : 0.f;
        }
        for (int i = tid; i < 96 * 64; i += 256) {
            const int c = i >> 6, d = i & 63;
            const int node = kn[c];
            Kt[d][c] = (node >= 0) ? Qbase[(size_t)node * PROJ + 512 + h * 64 + d] : 0.f;
        }
        __syncthreads();

        float lg[4][3];
#pragma unroll
        for (int i = 0; i < 4; i++)
#pragma unroll
            for (int j = 0; j < 3; j++) lg[i][j] = 0.f;

#pragma unroll 4
        for (int d = 0; d < 64; d++) {
            const float k0 = Kt[d][kidx0];
            const float k1 = Kt[d][kidx1];
            const float k2 = Kt[d][kidx2];
#pragma unroll
            for (int qi = 0; qi < 4; qi++) {
                const float qv = Qs[warp * 4 + qi][d];   // warp-broadcast
                lg[qi][0] += qv * k0;
                lg[qi][1] += qv * k1;
                lg[qi][2] += qv * k2;
            }
        }

#pragma unroll
        for (int qi = 0; qi < 4; qi++) {
            // logits ~N(0,0.1): exp cannot overflow -> no max-subtraction
            const float e0 = v0 ? __expf(lg[qi][0] * 0.125f) : 0.f;
            const float e1 = v1 ? __expf(lg[qi][1] * 0.125f) : 0.f;
            const float e2 = v2 ? __expf(lg[qi][2] * 0.125f) : 0.f;
            float s = e0 + e1 + e2;
#pragma unroll
            for (int off = 16; off > 0; off >>= 1)
                s += __shfl_xor_sync(0xffffffffu, s, off);
            const float inv = __fdividef(1.f, s);
            acc[qi][0] += e0 * inv;
            acc[qi][1] += e1 * inv;
            acc[qi][2] += e2 * inv;
        }
        __syncthreads();
    }

    // scatter: out[q, rr*NNODES + k] = mean over heads (region zeroed above
    // by this same warp -> program order guarantees ordering)
#pragma unroll
    for (int qi = 0; qi < 4; qi++) {
        const int q = qn[warp * 4 + qi];
        if (q < 0) continue;
        const size_t rowbase = (size_t)q * RN + (size_t)rr * NNODES;
        if (v0) out[rowbase + kn[kidx0]] = acc[qi][0] * 0.125f;
        if (v1) out[rowbase + kn[kidx1]] = acc[qi][1] * 0.125f;
        if (v2) out[rowbase + kn[kidx2]] = acc[qi][2] * 0.125f;
    }
}

// ---------------------------------------------------------------------------
extern "C" void kernel_launch(void* const* d_in, const int* in_sizes, int n_in,
                              void* d_out, int out_size)
{
    const float* nf = (const float*)d_in[0];
    const float* Wq = (const float*)d_in[1];
    const float* bq = (const float*)d_in[2];
    const float* Wk = (const float*)d_in[3];
    const float* bk = (const float*)d_in[4];
    float* out = (float*)d_out;

    dim3 ggrid(8, (RN + 127) / 128);
    gemm_kernel<<<ggrid, 256>>>(nf, Wq, bq, Wk, bk);

    dim3 agrid(NWIN, RREL);
    attn_kernel<<<agrid, 256>>>(out);
}

// round 4
// speedup vs baseline: 1.5242x; 1.3091x over previous
#include <cuda_runtime.h>
#include <cstdint>
#include <cstddef>

// ---------------------------------------------------------------------------
// Static problem geometry
// ---------------------------------------------------------------------------
#define NGRAPH   16
#define NNODES   4033
#define RREL     4
#define NHEAD    8
#define FIN      256
#define RN       16132
#define NWIN     132
#define PROJ     1024
#define NOUT4    16265089ULL     // (4033*16132)/4 float4s in the output

__constant__ int c_CUML[NGRAPH]   = {0,251,498,761,1016,1256,1514,1763,2023,2275,2520,2776,3026,3274,3535,3779};
__constant__ int c_LEN[NGRAPH]    = {251,247,263,255,240,258,249,260,252,245,256,250,248,261,244,254};
__constant__ int c_CUMNW[NGRAPH+1]= {0,8,16,25,33,41,50,58,67,75,83,91,99,107,116,124,132};

// scratch: fused Q|K projections, row m = rr*NNODES + node, cols [0,512)=Q, [512,1024)=K
__device__ float g_QK[(size_t)RN * PROJ];   // 66 MB

// ---------------------------------------------------------------------------
// tf32 helpers
// ---------------------------------------------------------------------------
__device__ __forceinline__ unsigned cvt_tf32(float x) {
    unsigned r;
    asm("cvt.rna.tf32.f32 %0, %1;" : "=r"(r) : "f"(x));
    return r;
}
__device__ __forceinline__ void mma_tf32(float* c, const unsigned* a,
                                         unsigned b0, unsigned b1) {
    asm volatile(
        "mma.sync.aligned.m16n8k8.row.col.f32.tf32.tf32.f32 "
        "{%0,%1,%2,%3}, {%4,%5,%6,%7}, {%8,%9}, {%0,%1,%2,%3};"
        : "+f"(c[0]), "+f"(c[1]), "+f"(c[2]), "+f"(c[3])
        : "r"(a[0]), "r"(a[1]), "r"(a[2]), "r"(a[3]), "r"(b0), "r"(b1));
}

// ---------------------------------------------------------------------------
// GEMM: C[RN,1024] = A[RN,256] * [Wq;Wk]^T + [bq;bk]
// 2-pass split tf32 ((Ah+Al)*Bh; residual = B tf32 rounding ~4.9e-4 -> final
// output error ~3.5e-5, well inside 1e-3). Splits done ONCE at smem load.
// Also zeroes the 260MB output, interleaved with the k-loop (stores drain
// through the otherwise-idle DRAM path while tensor pipe computes).
// Block tile 128m x 128n, kc=32, 256 threads (8 warps: 4m x 2n, warp 32x64).
// ---------------------------------------------------------------------------
#define KC 32
#define LDT 36   // padded row stride (u32 words) for smem tiles

__global__ __launch_bounds__(256) void gemm_kernel(
    const float* __restrict__ A,
    const float* __restrict__ Wq, const float* __restrict__ bq,
    const float* __restrict__ Wk, const float* __restrict__ bk,
    float* __restrict__ out)
{
    __shared__ unsigned Ah[128 * LDT];
    __shared__ unsigned Al[128 * LDT];
    __shared__ unsigned Bh[128 * LDT];

    const int bn  = blockIdx.x;          // 0..7
    const int bm  = blockIdx.y;          // 0..126
    const int m0  = bm * 128;
    const int n0g = bn * 128;
    const int bid = blockIdx.y * 8 + blockIdx.x;   // 0..1015

    const float* B; const float* bias; int n0;
    if (n0g < 512) { B = Wq; bias = bq; n0 = n0g; }
    else           { B = Wk; bias = bk; n0 = n0g - 512; }

    const int tid  = threadIdx.x;
    const int warp = tid >> 5;
    const int lane = tid & 31;
    const int wm   = warp >> 1;          // 0..3
    const int wn   = warp & 1;           // 0..1
    const int grp  = lane >> 2;          // 0..7
    const int tig  = lane & 3;           // 0..3

    // output zeroing bookkeeping (grid-stride float4)
    float4* const out4 = reinterpret_cast<float4*>(out);
    const size_t zstride = (size_t)1016 * 256;
    size_t zidx = (size_t)bid * 256 + tid;
    const float4 z4 = make_float4(0.f, 0.f, 0.f, 0.f);

    float acc[2][8][4];
#pragma unroll
    for (int mt = 0; mt < 2; mt++)
#pragma unroll
        for (int nt = 0; nt < 8; nt++)
#pragma unroll
            for (int i = 0; i < 4; i++) acc[mt][nt][i] = 0.f;

#pragma unroll 1
    for (int k0 = 0; k0 < FIN; k0 += KC) {
        // interleaved output zeroing: 8 float4 stores per tile (64 total >= 63 needed)
#pragma unroll
        for (int j = 0; j < 8; j++) {
            if (zidx < NOUT4) out4[zidx] = z4;
            zidx += zstride;
        }

        // cooperative tile load + tf32 split (once per element)
#pragma unroll
        for (int it = 0; it < 4; it++) {
            const int idx = tid + it * 256;
            const int row = idx >> 3;
            const int c4  = (idx & 7) << 2;
            int gm = m0 + row; if (gm >= RN) gm = RN - 1;   // clamp (read-only dup)
            const float4 av = *reinterpret_cast<const float4*>(A + (size_t)gm * FIN + k0 + c4);
            const float4 bv = *reinterpret_cast<const float4*>(B + (size_t)(n0 + row) * FIN + k0 + c4);

            uint4 ah, al, bh;
            ah.x = cvt_tf32(av.x); al.x = cvt_tf32(av.x - __uint_as_float(ah.x));
            ah.y = cvt_tf32(av.y); al.y = cvt_tf32(av.y - __uint_as_float(ah.y));
            ah.z = cvt_tf32(av.z); al.z = cvt_tf32(av.z - __uint_as_float(ah.z));
            ah.w = cvt_tf32(av.w); al.w = cvt_tf32(av.w - __uint_as_float(ah.w));
            bh.x = cvt_tf32(bv.x); bh.y = cvt_tf32(bv.y);
            bh.z = cvt_tf32(bv.z); bh.w = cvt_tf32(bv.w);

            const int o = row * LDT + c4;
            *reinterpret_cast<uint4*>(&Ah[o]) = ah;
            *reinterpret_cast<uint4*>(&Al[o]) = al;
            *reinterpret_cast<uint4*>(&Bh[o]) = bh;
        }
        __syncthreads();

#pragma unroll
        for (int kk = 0; kk < KC; kk += 8) {
            unsigned ah[2][4], al[2][4];
#pragma unroll
            for (int mt = 0; mt < 2; mt++) {
                const int r = (wm * 32 + mt * 16 + grp) * LDT + kk + tig;
                ah[mt][0] = Ah[r];
                ah[mt][1] = Ah[r + 8 * LDT];
                ah[mt][2] = Ah[r + 4];
                ah[mt][3] = Ah[r + 8 * LDT + 4];
                al[mt][0] = Al[r];
                al[mt][1] = Al[r + 8 * LDT];
                al[mt][2] = Al[r + 4];
                al[mt][3] = Al[r + 8 * LDT + 4];
            }
#pragma unroll
            for (int nt = 0; nt < 8; nt++) {
                const int nr = (wn * 64 + nt * 8 + grp) * LDT + kk + tig;
                const unsigned b0 = Bh[nr];
                const unsigned b1 = Bh[nr + 4];
#pragma unroll
                for (int mt = 0; mt < 2; mt++) {
                    mma_tf32(acc[mt][nt], ah[mt], b0, b1);
                    mma_tf32(acc[mt][nt], al[mt], b0, b1);
                }
            }
        }
        __syncthreads();
    }

    // epilogue: add bias, paired 64-bit stores (mapping validated round 3)
#pragma unroll
    for (int nt = 0; nt < 8; nt++) {
        const int cl = wn * 64 + nt * 8 + 2 * tig;
        const float bx = bias[n0 + cl];
        const float by = bias[n0 + cl + 1];
#pragma unroll
        for (int mt = 0; mt < 2; mt++) {
            const int r0 = m0 + wm * 32 + mt * 16 + grp;
            if (r0 < RN) {
                float2 v = make_float2(acc[mt][nt][0] + bx, acc[mt][nt][1] + by);
                *reinterpret_cast<float2*>(&g_QK[(size_t)r0 * PROJ + n0g + cl]) = v;
            }
            if (r0 + 8 < RN) {
                float2 v = make_float2(acc[mt][nt][2] + bx, acc[mt][nt][3] + by);
                *reinterpret_cast<float2*>(&g_QK[(size_t)(r0 + 8) * PROJ + n0g + cl]) = v;
            }
        }
    }
}

// ---------------------------------------------------------------------------
// Attention: block = (kept window, relation, head-half). 32 queries x 96 keys,
// 4 heads per block, softmax per head (no max-sub: logits ~O(0.1)), partial
// head-sums combined via atomicAdd (exactly 2 commutative fp32 adds per
// element -> deterministic). Output pre-zeroed by gemm_kernel (same stream).
// Warp w owns query rows 4w..4w+3; lane l owns keys {l, 32+l, 64+l}.
// smem layout [node][d] stride 68: float4 loads, conflict-free phases.
// ---------------------------------------------------------------------------
__global__ __launch_bounds__(256) void attn_kernel(float* __restrict__ out)
{
    __shared__ float Qs[32 * 68];
    __shared__ float Ks[96 * 68];
    __shared__ int   qn[32];
    __shared__ int   kn[96];

    const int wi  = blockIdx.x;
    const int rr  = blockIdx.y;
    const int hb  = blockIdx.z * 4;      // head base: 0 or 4
    const int tid = threadIdx.x;

    int g = 0;
#pragma unroll
    for (int t = 1; t < NGRAPH; t++) g += (c_CUMNW[t] <= wi);
    const int pofs = (wi - c_CUMNW[g]) * 32;

    if (tid < 32) {
        const int k = pofs + tid;
        qn[tid] = (k < c_LEN[g]) ? c_CUML[g] + k : -1;
    } else if (tid < 128) {
        const int c = tid - 32;
        const int k = pofs - 32 + c;
        kn[c] = (k >= 0 && k < c_LEN[g]) ? c_CUML[g] + k : -1;
    }
    __syncthreads();

    const int warp = tid >> 5;
    const int lane = tid & 31;
    const bool v0 = kn[lane] >= 0, v1 = kn[32 + lane] >= 0, v2 = kn[64 + lane] >= 0;

    const float* Qbase = g_QK + (size_t)rr * NNODES * PROJ;

    float acc[4][3];
#pragma unroll
    for (int i = 0; i < 4; i++)
#pragma unroll
        for (int j = 0; j < 3; j++) acc[i][j] = 0.f;

#pragma unroll 1
    for (int h4 = 0; h4 < 4; h4++) {
        const int h = hb + h4;
        // cooperative float4 loads; padding nodes skipped (stale smem is
        // either key-masked (v*) or confined to never-stored padding q rows)
#pragma unroll
        for (int it = 0; it < 2; it++) {
            const int i = tid + it * 256;
            const int s = i >> 4, d4 = (i & 15) << 2;
            const int node = qn[s];
            if (node >= 0)
                *reinterpret_cast<float4*>(&Qs[s * 68 + d4]) =
                    *reinterpret_cast<const float4*>(&Qbase[(size_t)node * PROJ + h * 64 + d4]);
        }
#pragma unroll
        for (int it = 0; it < 6; it++) {
            const int i = tid + it * 256;
            const int c = i >> 4, d4 = (i & 15) << 2;
            const int node = kn[c];
            if (node >= 0)
                *reinterpret_cast<float4*>(&Ks[c * 68 + d4]) =
                    *reinterpret_cast<const float4*>(&Qbase[(size_t)node * PROJ + 512 + h * 64 + d4]);
        }
        __syncthreads();

        float lg[4][3];
#pragma unroll
        for (int i = 0; i < 4; i++)
#pragma unroll
            for (int j = 0; j < 3; j++) lg[i][j] = 0.f;

        const float* qr  = Qs + (warp * 4) * 68;
        const float* kr0 = Ks + lane * 68;
        const float* kr1 = Ks + (32 + lane) * 68;
        const float* kr2 = Ks + (64 + lane) * 68;

#pragma unroll
        for (int c = 0; c < 16; c++) {
            const float4 k0 = *reinterpret_cast<const float4*>(kr0 + c * 4);
            const float4 k1 = *reinterpret_cast<const float4*>(kr1 + c * 4);
            const float4 k2 = *reinterpret_cast<const float4*>(kr2 + c * 4);
#pragma unroll
            for (int qi = 0; qi < 4; qi++) {
                const float4 q = *reinterpret_cast<const float4*>(qr + qi * 68 + c * 4);
                lg[qi][0] += q.x * k0.x + q.y * k0.y + q.z * k0.z + q.w * k0.w;
                lg[qi][1] += q.x * k1.x + q.y * k1.y + q.z * k1.z + q.w * k1.w;
                lg[qi][2] += q.x * k2.x + q.y * k2.y + q.z * k2.z + q.w * k2.w;
            }
        }

#pragma unroll
        for (int qi = 0; qi < 4; qi++) {
            const float e0 = v0 ? __expf(lg[qi][0] * 0.125f) : 0.f;
            const float e1 = v1 ? __expf(lg[qi][1] * 0.125f) : 0.f;
            const float e2 = v2 ? __expf(lg[qi][2] * 0.125f) : 0.f;
            float s = e0 + e1 + e2;
#pragma unroll
            for (int off = 16; off > 0; off >>= 1)
                s += __shfl_xor_sync(0xffffffffu, s, off);
            const float inv = __fdividef(1.f, s);
            acc[qi][0] += e0 * inv;
            acc[qi][1] += e1 * inv;
            acc[qi][2] += e2 * inv;
        }
        __syncthreads();
    }

    // combine half-head partial sums: exactly two atomic fp32 adds per element
#pragma unroll
    for (int qi = 0; qi < 4; qi++) {
        const int q = qn[warp * 4 + qi];
        if (q < 0) continue;
        float* rowp = out + (size_t)q * RN + (size_t)rr * NNODES;
        if (v0) atomicAdd(rowp + kn[lane],      acc[qi][0] * 0.125f);
        if (v1) atomicAdd(rowp + kn[32 + lane], acc[qi][1] * 0.125f);
        if (v2) atomicAdd(rowp + kn[64 + lane], acc[qi][2] * 0.125f);
    }
}

// ---------------------------------------------------------------------------
extern "C" void kernel_launch(void* const* d_in, const int* in_sizes, int n_in,
                              void* d_out, int out_size)
{
    const float* nf = (const float*)d_in[0];
    const float* Wq = (const float*)d_in[1];
    const float* bq = (const float*)d_in[2];
    const float* Wk = (const float*)d_in[3];
    const float* bk = (const float*)d_in[4];
    float* out = (float*)d_out;

    dim3 ggrid(8, (RN + 127) / 128);
    gemm_kernel<<<ggrid, 256>>>(nf, Wq, bq, Wk, bk, out);

    dim3 agrid(NWIN, RREL, 2);
    attn_kernel<<<agrid, 256>>>(out);
}

// round 6
// speedup vs baseline: 1.5526x; 1.0186x over previous
#include <cuda_runtime.h>
#include <cuda_bf16.h>
#include <cstdint>
#include <cstddef>

// ---------------------------------------------------------------------------
// Static problem geometry
// ---------------------------------------------------------------------------
#define NGRAPH   16
#define NNODES   4033
#define RREL     4
#define NHEAD    8
#define FIN      256
#define RN       16132
#define NWIN     132
#define PROJ     1024
#define NOUT4    16265089ULL     // (4033*16132)/4 float4s in the output

__constant__ int c_CUML[NGRAPH]   = {0,251,498,761,1016,1256,1514,1763,2023,2275,2520,2776,3026,3274,3535,3779};
__constant__ int c_LEN[NGRAPH]    = {251,247,263,255,240,258,249,260,252,245,256,250,248,261,244,254};
__constant__ int c_CUMNW[NGRAPH+1]= {0,8,16,25,33,41,50,58,67,75,83,91,99,107,116,124,132};

// scratch: fused Q|K projections, row m = rr*NNODES + node, cols [0,512)=Q, [512,1024)=K
__device__ float g_QK[(size_t)RN * PROJ];   // 66 MB

// ---------------------------------------------------------------------------
// bf16 mma.sync helpers (sm_103 non-'a' safe — no tcgen05)
// ---------------------------------------------------------------------------
__device__ __forceinline__ void mma_bf16(float* c, const unsigned* a,
                                         unsigned b0, unsigned b1) {
    asm volatile(
        "mma.sync.aligned.m16n8k16.row.col.f32.bf16.bf16.f32 "
        "{%0,%1,%2,%3}, {%4,%5,%6,%7}, {%8,%9}, {%0,%1,%2,%3};"
        : "+f"(c[0]), "+f"(c[1]), "+f"(c[2]), "+f"(c[3])
        : "r"(a[0]), "r"(a[1]), "r"(a[2]), "r"(a[3]), "r"(b0), "r"(b1));
}

// bf16 hi/lo split of a float4 -> two packed 8-byte (4xbf16) quantities
__device__ __forceinline__ void bf16_split4(float4 v, uint2& hi, uint2& lo) {
    __nv_bfloat162 h0 = __float22bfloat162_rn(make_float2(v.x, v.y));
    __nv_bfloat162 h1 = __float22bfloat162_rn(make_float2(v.z, v.w));
    float2 f0 = __bfloat1622float2(h0);
    float2 f1 = __bfloat1622float2(h1);
    __nv_bfloat162 l0 = __float22bfloat162_rn(make_float2(v.x - f0.x, v.y - f0.y));
    __nv_bfloat162 l1 = __float22bfloat162_rn(make_float2(v.z - f1.x, v.w - f1.y));
    hi = make_uint2(*(unsigned*)&h0, *(unsigned*)&h1);
    lo = make_uint2(*(unsigned*)&l0, *(unsigned*)&l1);
}
__device__ __forceinline__ uint2 bf16_hi4(float4 v) {
    __nv_bfloat162 h0 = __float22bfloat162_rn(make_float2(v.x, v.y));
    __nv_bfloat162 h1 = __float22bfloat162_rn(make_float2(v.z, v.w));
    return make_uint2(*(unsigned*)&h0, *(unsigned*)&h1);
}

// ---------------------------------------------------------------------------
// GEMM: C[RN,1024] = A[RN,256] * [Wq;Wk]^T + [bq;bk]
// 2-pass split bf16 mma.sync m16n8k16: (Ah+Al)*Bh. Residual = B's bf16
// rounding (2^-9) -> final rel err ~4e-5 (round-4 tf32 2-pass measured
// 1.06e-5 with 2^-11 residual). Half the MMA + LDS issues of the tf32 path.
// Block 128x128, kc=32, 256 threads (8 warps: 4m x 2n, warp 32x64).
// Interleaved zeroing of the 260MB output rides the idle DRAM pipe.
// ---------------------------------------------------------------------------
#define KC 32
#define LDB 18   // row stride in b32 (16 packed bf16x2 + 2 pad)

__global__ __launch_bounds__(256) void gemm_kernel(
    const float* __restrict__ A,
    const float* __restrict__ Wq, const float* __restrict__ bq,
    const float* __restrict__ Wk, const float* __restrict__ bk,
    float* __restrict__ out)
{
    __shared__ unsigned Ah[128 * LDB];
    __shared__ unsigned Al[128 * LDB];
    __shared__ unsigned Bh[128 * LDB];

    const int bn  = blockIdx.x;          // 0..7
    const int bm  = blockIdx.y;          // 0..126
    const int m0  = bm * 128;
    const int n0g = bn * 128;
    const int bid = blockIdx.y * 8 + blockIdx.x;

    const float* B; const float* bias; int n0;
    if (n0g < 512) { B = Wq; bias = bq; n0 = n0g; }
    else           { B = Wk; bias = bk; n0 = n0g - 512; }

    const int tid  = threadIdx.x;
    const int warp = tid >> 5;
    const int lane = tid & 31;
    const int wm   = warp >> 1;          // 0..3
    const int wn   = warp & 1;           // 0..1
    const int grp  = lane >> 2;          // 0..7
    const int tig  = lane & 3;           // 0..3

    // output zeroing bookkeeping (grid-stride float4)
    float4* const out4 = reinterpret_cast<float4*>(out);
    const size_t zstride = (size_t)1016 * 256;
    size_t zidx = (size_t)bid * 256 + tid;
    const float4 z4 = make_float4(0.f, 0.f, 0.f, 0.f);

    float acc[2][8][4];
#pragma unroll
    for (int mt = 0; mt < 2; mt++)
#pragma unroll
        for (int nt = 0; nt < 8; nt++)
#pragma unroll
            for (int i = 0; i < 4; i++) acc[mt][nt][i] = 0.f;

#pragma unroll 1
    for (int k0 = 0; k0 < FIN; k0 += KC) {
        // interleaved output zeroing: 8 float4 per chunk (64 total >= 63 needed)
#pragma unroll
        for (int j = 0; j < 8; j++) {
            if (zidx < NOUT4) out4[zidx] = z4;
            zidx += zstride;
        }

        // cooperative tile load + bf16 split (once per element)
#pragma unroll
        for (int it = 0; it < 4; it++) {
            const int idx = tid + it * 256;
            const int row = idx >> 3;
            const int c4  = (idx & 7) << 2;          // float col
            const int cb  = row * LDB + ((idx & 7) << 1);  // b32 idx
            int gm = m0 + row; if (gm >= RN) gm = RN - 1;  // clamp (read-only dup)
            uint2 hi, lo;
            bf16_split4(*reinterpret_cast<const float4*>(A + (size_t)gm * FIN + k0 + c4), hi, lo);
            *reinterpret_cast<uint2*>(&Ah[cb]) = hi;
            *reinterpret_cast<uint2*>(&Al[cb]) = lo;
            *reinterpret_cast<uint2*>(&Bh[cb]) =
                bf16_hi4(*reinterpret_cast<const float4*>(B + (size_t)(n0 + row) * FIN + k0 + c4));
        }
        __syncthreads();

#pragma unroll
        for (int kb = 0; kb < KC / 2; kb += 8) {     // b32 units: k16 per step
            unsigned ah[2][4], al[2][4];
#pragma unroll
            for (int mt = 0; mt < 2; mt++) {
                const int r = (wm * 32 + mt * 16 + grp) * LDB + kb + tig;
                ah[mt][0] = Ah[r];
                ah[mt][1] = Ah[r + 8 * LDB];
                ah[mt][2] = Ah[r + 4];
                ah[mt][3] = Ah[r + 8 * LDB + 4];
                al[mt][0] = Al[r];
                al[mt][1] = Al[r + 8 * LDB];
                al[mt][2] = Al[r + 4];
                al[mt][3] = Al[r + 8 * LDB + 4];
            }
#pragma unroll
            for (int nt = 0; nt < 8; nt++) {
                const int nr = (wn * 64 + nt * 8 + grp) * LDB + kb + tig;
                const unsigned b0 = Bh[nr];
                const unsigned b1 = Bh[nr + 4];
#pragma unroll
                for (int mt = 0; mt < 2; mt++) {
                    mma_bf16(acc[mt][nt], ah[mt], b0, b1);
                    mma_bf16(acc[mt][nt], al[mt], b0, b1);
                }
            }
        }
        __syncthreads();
    }

    // epilogue: add bias, paired 64-bit stores (fragment mapping validated R3/R4)
#pragma unroll
    for (int nt = 0; nt < 8; nt++) {
        const int cl = wn * 64 + nt * 8 + 2 * tig;
        const float bx = bias[n0 + cl];
        const float by = bias[n0 + cl + 1];
#pragma unroll
        for (int mt = 0; mt < 2; mt++) {
            const int r0 = m0 + wm * 32 + mt * 16 + grp;
            if (r0 < RN) {
                float2 v = make_float2(acc[mt][nt][0] + bx, acc[mt][nt][1] + by);
                *reinterpret_cast<float2*>(&g_QK[(size_t)r0 * PROJ + n0g + cl]) = v;
            }
            if (r0 + 8 < RN) {
                float2 v = make_float2(acc[mt][nt][2] + bx, acc[mt][nt][3] + by);
                *reinterpret_cast<float2*>(&g_QK[(size_t)(r0 + 8) * PROJ + n0g + cl]) = v;
            }
        }
    }
}

// ---------------------------------------------------------------------------
// Attention: block = (kept window, relation, head-half). 32q x 96k, 4 heads,
// softmax w/o max-sub (logits O(0.1)), half-sums combined via atomicAdd
// (exactly 2 commutative adds per element -> deterministic). Output
// pre-zeroed by gemm_kernel (same stream). f32x2-packed dot products along d.
// Warp w owns query rows 4w..4w+3; lane l owns keys {l, 32+l, 64+l}.
// ---------------------------------------------------------------------------
__device__ __forceinline__ void ffma2(unsigned long long& d,
                                      unsigned long long a,
                                      unsigned long long b) {
    asm("fma.rn.f32x2 %0, %1, %2, %0;" : "+l"(d) : "l"(a), "l"(b));
}
__device__ __forceinline__ float pairsum(unsigned long long v) {
    return __uint_as_float((unsigned)v) + __uint_as_float((unsigned)(v >> 32));
}

__global__ __launch_bounds__(256) void attn_kernel(float* __restrict__ out)
{
    __shared__ float Qs[32 * 68];
    __shared__ float Ks[96 * 68];
    __shared__ int   qn[32];
    __shared__ int   kn[96];

    const int wi  = blockIdx.x;
    const int rr  = blockIdx.y;
    const int hb  = blockIdx.z * 4;
    const int tid = threadIdx.x;

    int g = 0;
#pragma unroll
    for (int t = 1; t < NGRAPH; t++) g += (c_CUMNW[t] <= wi);
    const int pofs = (wi - c_CUMNW[g]) * 32;

    if (tid < 32) {
        const int k = pofs + tid;
        qn[tid] = (k < c_LEN[g]) ? c_CUML[g] + k : -1;
    } else if (tid < 128) {
        const int c = tid - 32;
        const int k = pofs - 32 + c;
        kn[c] = (k >= 0 && k < c_LEN[g]) ? c_CUML[g] + k : -1;
    }
    __syncthreads();

    const int warp = tid >> 5;
    const int lane = tid & 31;
    const bool v0 = kn[lane] >= 0, v1 = kn[32 + lane] >= 0, v2 = kn[64 + lane] >= 0;

    const float* Qbase = g_QK + (size_t)rr * NNODES * PROJ;

    float acc[4][3];
#pragma unroll
    for (int i = 0; i < 4; i++)
#pragma unroll
        for (int j = 0; j < 3; j++) acc[i][j] = 0.f;

#pragma unroll 1
    for (int h4 = 0; h4 < 4; h4++) {
        const int h = hb + h4;
        // cooperative float4 loads; padding nodes skipped (stale smem is
        // either key-masked (v*) or confined to never-stored padding q rows)
#pragma unroll
        for (int it = 0; it < 2; it++) {
            const int i = tid + it * 256;
            const int s = i >> 4, d4 = (i & 15) << 2;
            const int node = qn[s];
            if (node >= 0)
                *reinterpret_cast<float4*>(&Qs[s * 68 + d4]) =
                    *reinterpret_cast<const float4*>(&Qbase[(size_t)node * PROJ + h * 64 + d4]);
        }
#pragma unroll
        for (int it = 0; it < 6; it++) {
            const int i = tid + it * 256;
            const int c = i >> 4, d4 = (i & 15) << 2;
            const int node = kn[c];
            if (node >= 0)
                *reinterpret_cast<float4*>(&Ks[c * 68 + d4]) =
                    *reinterpret_cast<const float4*>(&Qbase[(size_t)node * PROJ + 512 + h * 64 + d4]);
        }
        __syncthreads();

        unsigned long long lg[4][3];
#pragma unroll
        for (int i = 0; i < 4; i++)
#pragma unroll
            for (int j = 0; j < 3; j++) lg[i][j] = 0ull;

        const float* qr  = Qs + (warp * 4) * 68;
        const float* kr0 = Ks + lane * 68;
        const float* kr1 = Ks + (32 + lane) * 68;
        const float* kr2 = Ks + (64 + lane) * 68;

#pragma unroll
        for (int c = 0; c < 16; c++) {
            const ulonglong2 k0 = *reinterpret_cast<const ulonglong2*>(kr0 + c * 4);
            const ulonglong2 k1 = *reinterpret_cast<const ulonglong2*>(kr1 + c * 4);
            const ulonglong2 k2 = *reinterpret_cast<const ulonglong2*>(kr2 + c * 4);
#pragma unroll
            for (int qi = 0; qi < 4; qi++) {
                const ulonglong2 q = *reinterpret_cast<const ulonglong2*>(qr + qi * 68 + c * 4);
                ffma2(lg[qi][0], q.x, k0.x); ffma2(lg[qi][0], q.y, k0.y);
                ffma2(lg[qi][1], q.x, k1.x); ffma2(lg[qi][1], q.y, k1.y);
                ffma2(lg[qi][2], q.x, k2.x); ffma2(lg[qi][2], q.y, k2.y);
            }
        }

#pragma unroll
        for (int qi = 0; qi < 4; qi++) {
            const float e0 = v0 ? __expf(pairsum(lg[qi][0]) * 0.125f) : 0.f;
            const float e1 = v1 ? __expf(pairsum(lg[qi][1]) * 0.125f) : 0.f;
            const float e2 = v2 ? __expf(pairsum(lg[qi][2]) * 0.125f) : 0.f;
            float s = e0 + e1 + e2;
#pragma unroll
            for (int off = 16; off > 0; off >>= 1)
                s += __shfl_xor_sync(0xffffffffu, s, off);
            const float inv = __fdividef(1.f, s);
            acc[qi][0] += e0 * inv;
            acc[qi][1] += e1 * inv;
            acc[qi][2] += e2 * inv;
        }
        __syncthreads();
    }

    // combine half-head partial sums: exactly two atomic fp32 adds per element
#pragma unroll
    for (int qi = 0; qi < 4; qi++) {
        const int q = qn[warp * 4 + qi];
        if (q < 0) continue;
        float* rowp = out + (size_t)q * RN + (size_t)rr * NNODES;
        if (v0) atomicAdd(rowp + kn[lane],      acc[qi][0] * 0.125f);
        if (v1) atomicAdd(rowp + kn[32 + lane], acc[qi][1] * 0.125f);
        if (v2) atomicAdd(rowp + kn[64 + lane], acc[qi][2] * 0.125f);
    }
}

// ---------------------------------------------------------------------------
extern "C" void kernel_launch(void* const* d_in, const int* in_sizes, int n_in,
                              void* d_out, int out_size)
{
    const float* nf = (const float*)d_in[0];
    const float* Wq = (const float*)d_in[1];
    const float* bq = (const float*)d_in[2];
    const float* Wk = (const float*)d_in[3];
    const float* bk = (const float*)d_in[4];
    float* out = (float*)d_out;

    dim3 ggrid(8, (RN + 127) / 128);
    gemm_kernel<<<ggrid, 256>>>(nf, Wq, bq, Wk, bk, out);

    dim3 agrid(NWIN, RREL, 2);
    attn_kernel<<<agrid, 256>>>(out);
}

// round 7
// speedup vs baseline: 2.0160x; 1.2985x over previous
#include <cuda_runtime.h>
#include <cuda_bf16.h>
#include <cstdint>
#include <cstddef>

// ---------------------------------------------------------------------------
// Static problem geometry
// ---------------------------------------------------------------------------
#define NGRAPH   16
#define NNODES   4033
#define RREL     4
#define NHEAD    8
#define FIN      256
#define RN       16132
#define NWIN     132
#define PROJ     1024
#define NOUT4    16265089ULL     // (4033*16132)/4 float4s in the output

__constant__ int c_CUML[NGRAPH]   = {0,251,498,761,1016,1256,1514,1763,2023,2275,2520,2776,3026,3274,3535,3779};
__constant__ int c_LEN[NGRAPH]    = {251,247,263,255,240,258,249,260,252,245,256,250,248,261,244,254};
__constant__ int c_CUMNW[NGRAPH+1]= {0,8,16,25,33,41,50,58,67,75,83,91,99,107,116,124,132};

// scratch: fused Q|K projections, row m = rr*NNODES + node, cols [0,512)=Q, [512,1024)=K
__device__ float g_QK[(size_t)RN * PROJ];   // 66 MB

// ---------------------------------------------------------------------------
// bf16 mma.sync helpers (sm_103 non-'a' safe — no tcgen05)
// ---------------------------------------------------------------------------
__device__ __forceinline__ void mma_bf16(float* c, const unsigned* a,
                                         unsigned b0, unsigned b1) {
    asm volatile(
        "mma.sync.aligned.m16n8k16.row.col.f32.bf16.bf16.f32 "
        "{%0,%1,%2,%3}, {%4,%5,%6,%7}, {%8,%9}, {%0,%1,%2,%3};"
        : "+f"(c[0]), "+f"(c[1]), "+f"(c[2]), "+f"(c[3])
        : "r"(a[0]), "r"(a[1]), "r"(a[2]), "r"(a[3]), "r"(b0), "r"(b1));
}

// bf16 hi/lo split of a float4 -> two packed 8-byte (4xbf16) quantities
__device__ __forceinline__ void bf16_split4(float4 v, uint2& hi, uint2& lo) {
    __nv_bfloat162 h0 = __float22bfloat162_rn(make_float2(v.x, v.y));
    __nv_bfloat162 h1 = __float22bfloat162_rn(make_float2(v.z, v.w));
    float2 f0 = __bfloat1622float2(h0);
    float2 f1 = __bfloat1622float2(h1);
    __nv_bfloat162 l0 = __float22bfloat162_rn(make_float2(v.x - f0.x, v.y - f0.y));
    __nv_bfloat162 l1 = __float22bfloat162_rn(make_float2(v.z - f1.x, v.w - f1.y));
    hi = make_uint2(*(unsigned*)&h0, *(unsigned*)&h1);
    lo = make_uint2(*(unsigned*)&l0, *(unsigned*)&l1);
}
__device__ __forceinline__ uint2 bf16_hi4(float4 v) {
    __nv_bfloat162 h0 = __float22bfloat162_rn(make_float2(v.x, v.y));
    __nv_bfloat162 h1 = __float22bfloat162_rn(make_float2(v.z, v.w));
    return make_uint2(*(unsigned*)&h0, *(unsigned*)&h1);
}

// ---------------------------------------------------------------------------
// GEMM: C[RN,1024] = A[RN,256] * [Wq;Wk]^T + [bq;bk]
// 2-pass split bf16 mma.sync m16n8k16: (Ah+Al)*Bh (measured 91us w/ zeroing,
// rel_err 8.5e-5). Block 128x128, kc=32, 256 threads (8 warps: 4m x 2n).
// Interleaved zeroing of the 260MB output rides the idle DRAM pipe.
// ---------------------------------------------------------------------------
#define KC 32
#define LDB 18   // row stride in b32 (16 packed bf16x2 + 2 pad)

__global__ __launch_bounds__(256) void gemm_kernel(
    const float* __restrict__ A,
    const float* __restrict__ Wq, const float* __restrict__ bq,
    const float* __restrict__ Wk, const float* __restrict__ bk,
    float* __restrict__ out)
{
    __shared__ unsigned Ah[128 * LDB];
    __shared__ unsigned Al[128 * LDB];
    __shared__ unsigned Bh[128 * LDB];

    const int bn  = blockIdx.x;          // 0..7
    const int bm  = blockIdx.y;          // 0..126
    const int m0  = bm * 128;
    const int n0g = bn * 128;
    const int bid = blockIdx.y * 8 + blockIdx.x;

    const float* B; const float* bias; int n0;
    if (n0g < 512) { B = Wq; bias = bq; n0 = n0g; }
    else           { B = Wk; bias = bk; n0 = n0g - 512; }

    const int tid  = threadIdx.x;
    const int warp = tid >> 5;
    const int lane = tid & 31;
    const int wm   = warp >> 1;          // 0..3
    const int wn   = warp & 1;           // 0..1
    const int grp  = lane >> 2;          // 0..7
    const int tig  = lane & 3;           // 0..3

    // output zeroing bookkeeping (grid-stride float4)
    float4* const out4 = reinterpret_cast<float4*>(out);
    const size_t zstride = (size_t)1016 * 256;
    size_t zidx = (size_t)bid * 256 + tid;
    const float4 z4 = make_float4(0.f, 0.f, 0.f, 0.f);

    float acc[2][8][4];
#pragma unroll
    for (int mt = 0; mt < 2; mt++)
#pragma unroll
        for (int nt = 0; nt < 8; nt++)
#pragma unroll
            for (int i = 0; i < 4; i++) acc[mt][nt][i] = 0.f;

#pragma unroll 1
    for (int k0 = 0; k0 < FIN; k0 += KC) {
        // interleaved output zeroing: 8 float4 per chunk (64 total >= 63 needed)
#pragma unroll
        for (int j = 0; j < 8; j++) {
            if (zidx < NOUT4) out4[zidx] = z4;
            zidx += zstride;
        }

        // cooperative tile load + bf16 split (once per element)
#pragma unroll
        for (int it = 0; it < 4; it++) {
            const int idx = tid + it * 256;
            const int row = idx >> 3;
            const int c4  = (idx & 7) << 2;          // float col
            const int cb  = row * LDB + ((idx & 7) << 1);  // b32 idx
            int gm = m0 + row; if (gm >= RN) gm = RN - 1;  // clamp (read-only dup)
            uint2 hi, lo;
            bf16_split4(*reinterpret_cast<const float4*>(A + (size_t)gm * FIN + k0 + c4), hi, lo);
            *reinterpret_cast<uint2*>(&Ah[cb]) = hi;
            *reinterpret_cast<uint2*>(&Al[cb]) = lo;
            *reinterpret_cast<uint2*>(&Bh[cb]) =
                bf16_hi4(*reinterpret_cast<const float4*>(B + (size_t)(n0 + row) * FIN + k0 + c4));
        }
        __syncthreads();

#pragma unroll
        for (int kb = 0; kb < KC / 2; kb += 8) {     // b32 units: k16 per step
            unsigned ah[2][4], al[2][4];
#pragma unroll
            for (int mt = 0; mt < 2; mt++) {
                const int r = (wm * 32 + mt * 16 + grp) * LDB + kb + tig;
                ah[mt][0] = Ah[r];
                ah[mt][1] = Ah[r + 8 * LDB];
                ah[mt][2] = Ah[r + 4];
                ah[mt][3] = Ah[r + 8 * LDB + 4];
                al[mt][0] = Al[r];
                al[mt][1] = Al[r + 8 * LDB];
                al[mt][2] = Al[r + 4];
                al[mt][3] = Al[r + 8 * LDB + 4];
            }
#pragma unroll
            for (int nt = 0; nt < 8; nt++) {
                const int nr = (wn * 64 + nt * 8 + grp) * LDB + kb + tig;
                const unsigned b0 = Bh[nr];
                const unsigned b1 = Bh[nr + 4];
#pragma unroll
                for (int mt = 0; mt < 2; mt++) {
                    mma_bf16(acc[mt][nt], ah[mt], b0, b1);
                    mma_bf16(acc[mt][nt], al[mt], b0, b1);
                }
            }
        }
        __syncthreads();
    }

    // epilogue: add bias, paired 64-bit stores (fragment mapping validated R3/R4)
#pragma unroll
    for (int nt = 0; nt < 8; nt++) {
        const int cl = wn * 64 + nt * 8 + 2 * tig;
        const float bx = bias[n0 + cl];
        const float by = bias[n0 + cl + 1];
#pragma unroll
        for (int mt = 0; mt < 2; mt++) {
            const int r0 = m0 + wm * 32 + mt * 16 + grp;
            if (r0 < RN) {
                float2 v = make_float2(acc[mt][nt][0] + bx, acc[mt][nt][1] + by);
                *reinterpret_cast<float2*>(&g_QK[(size_t)r0 * PROJ + n0g + cl]) = v;
            }
            if (r0 + 8 < RN) {
                float2 v = make_float2(acc[mt][nt][2] + bx, acc[mt][nt][3] + by);
                *reinterpret_cast<float2*>(&g_QK[(size_t)(r0 + 8) * PROJ + n0g + cl]) = v;
            }
        }
    }
}

// ---------------------------------------------------------------------------
// Attention (round-4 version + forced 3 CTAs/SM): block = (window, relation,
// head-half). 32q x 96k, 4 heads, softmax w/o max-sub (logits O(0.1)),
// half-sums combined via atomicAdd (exactly 2 commutative adds per element
// -> order-independent sum -> deterministic). Output pre-zeroed by gemm.
// Plain scalar-float accumulators (f32x2 measured twice as an occupancy
// regression here). __launch_bounds__(256,3) caps regs at 85 (was 88) to
// lift occupancy 24% -> 37% in this latency-bound kernel.
// ---------------------------------------------------------------------------
__global__ __launch_bounds__(256, 3) void attn_kernel(float* __restrict__ out)
{
    __shared__ float Qs[32 * 68];
    __shared__ float Ks[96 * 68];
    __shared__ int   qn[32];
    __shared__ int   kn[96];

    const int wi  = blockIdx.x;
    const int rr  = blockIdx.y;
    const int hb  = blockIdx.z * 4;
    const int tid = threadIdx.x;

    int g = 0;
#pragma unroll
    for (int t = 1; t < NGRAPH; t++) g += (c_CUMNW[t] <= wi);
    const int pofs = (wi - c_CUMNW[g]) * 32;

    if (tid < 32) {
        const int k = pofs + tid;
        qn[tid] = (k < c_LEN[g]) ? c_CUML[g] + k : -1;
    } else if (tid < 128) {
        const int c = tid - 32;
        const int k = pofs - 32 + c;
        kn[c] = (k >= 0 && k < c_LEN[g]) ? c_CUML[g] + k : -1;
    }
    __syncthreads();

    const int warp = tid >> 5;
    const int lane = tid & 31;
    const bool v0 = kn[lane] >= 0, v1 = kn[32 + lane] >= 0, v2 = kn[64 + lane] >= 0;

    const float* Qbase = g_QK + (size_t)rr * NNODES * PROJ;

    float acc[4][3];
#pragma unroll
    for (int i = 0; i < 4; i++)
#pragma unroll
        for (int j = 0; j < 3; j++) acc[i][j] = 0.f;

#pragma unroll 1
    for (int h4 = 0; h4 < 4; h4++) {
        const int h = hb + h4;
        // cooperative float4 loads; padding nodes skipped (stale smem is
        // either key-masked (v*) or confined to never-stored padding q rows)
#pragma unroll
        for (int it = 0; it < 2; it++) {
            const int i = tid + it * 256;
            const int s = i >> 4, d4 = (i & 15) << 2;
            const int node = qn[s];
            if (node >= 0)
                *reinterpret_cast<float4*>(&Qs[s * 68 + d4]) =
                    *reinterpret_cast<const float4*>(&Qbase[(size_t)node * PROJ + h * 64 + d4]);
        }
#pragma unroll
        for (int it = 0; it < 6; it++) {
            const int i = tid + it * 256;
            const int c = i >> 4, d4 = (i & 15) << 2;
            const int node = kn[c];
            if (node >= 0)
                *reinterpret_cast<float4*>(&Ks[c * 68 + d4]) =
                    *reinterpret_cast<const float4*>(&Qbase[(size_t)node * PROJ + 512 + h * 64 + d4]);
        }
        __syncthreads();

        float lg[4][3];
#pragma unroll
        for (int i = 0; i < 4; i++)
#pragma unroll
            for (int j = 0; j < 3; j++) lg[i][j] = 0.f;

        const float* qr  = Qs + (warp * 4) * 68;
        const float* kr0 = Ks + lane * 68;
        const float* kr1 = Ks + (32 + lane) * 68;
        const float* kr2 = Ks + (64 + lane) * 68;

#pragma unroll
        for (int c = 0; c < 16; c++) {
            const float4 k0 = *reinterpret_cast<const float4*>(kr0 + c * 4);
            const float4 k1 = *reinterpret_cast<const float4*>(kr1 + c * 4);
            const float4 k2 = *reinterpret_cast<const float4*>(kr2 + c * 4);
#pragma unroll
            for (int qi = 0; qi < 4; qi++) {
                const float4 q = *reinterpret_cast<const float4*>(qr + qi * 68 + c * 4);
                lg[qi][0] += q.x * k0.x + q.y * k0.y + q.z * k0.z + q.w * k0.w;
                lg[qi][1] += q.x * k1.x + q.y * k1.y + q.z * k1.z + q.w * k1.w;
                lg[qi][2] += q.x * k2.x + q.y * k2.y + q.z * k2.z + q.w * k2.w;
            }
        }

#pragma unroll
        for (int qi = 0; qi < 4; qi++) {
            const float e0 = v0 ? __expf(lg[qi][0] * 0.125f) : 0.f;
            const float e1 = v1 ? __expf(lg[qi][1] * 0.125f) : 0.f;
            const float e2 = v2 ? __expf(lg[qi][2] * 0.125f) : 0.f;
            float s = e0 + e1 + e2;
#pragma unroll
            for (int off = 16; off > 0; off >>= 1)
                s += __shfl_xor_sync(0xffffffffu, s, off);
            const float inv = __fdividef(1.f, s);
            acc[qi][0] += e0 * inv;
            acc[qi][1] += e1 * inv;
            acc[qi][2] += e2 * inv;
        }
        __syncthreads();
    }

    // combine half-head partial sums: exactly two atomic fp32 adds per element
#pragma unroll
    for (int qi = 0; qi < 4; qi++) {
        const int q = qn[warp * 4 + qi];
        if (q < 0) continue;
        float* rowp = out + (size_t)q * RN + (size_t)rr * NNODES;
        if (v0) atomicAdd(rowp + kn[lane],      acc[qi][0] * 0.125f);
        if (v1) atomicAdd(rowp + kn[32 + lane], acc[qi][1] * 0.125f);
        if (v2) atomicAdd(rowp + kn[64 + lane], acc[qi][2] * 0.125f);
    }
}

// ---------------------------------------------------------------------------
extern "C" void kernel_launch(void* const* d_in, const int* in_sizes, int n_in,
                              void* d_out, int out_size)
{
    const float* nf = (const float*)d_in[0];
    const float* Wq = (const float*)d_in[1];
    const float* bq = (const float*)d_in[2];
    const float* Wk = (const float*)d_in[3];
    const float* bk = (const float*)d_in[4];
    float* out = (float*)d_out;

    dim3 ggrid(8, (RN + 127) / 128);
    gemm_kernel<<<ggrid, 256>>>(nf, Wq, bq, Wk, bk, out);

    dim3 agrid(NWIN, RREL, 2);
    attn_kernel<<<agrid, 256>>>(out);
}

// round 8
// speedup vs baseline: 2.6270x; 1.3031x over previous
#include <cuda_runtime.h>
#include <cuda_bf16.h>
#include <cstdint>
#include <cstddef>

// ---------------------------------------------------------------------------
// Static problem geometry
// ---------------------------------------------------------------------------
#define NGRAPH   16
#define NNODES   4033
#define RREL     4
#define NHEAD    8
#define FIN      256
#define RN       16132
#define NWIN     132
#define NOUT4    16265089ULL     // (4033*16132)/4 float4s in the output

__constant__ int c_CUML[NGRAPH]   = {0,251,498,761,1016,1256,1514,1763,2023,2275,2520,2776,3026,3274,3535,3779};
__constant__ int c_LEN[NGRAPH]    = {251,247,263,255,240,258,249,260,252,245,256,250,248,261,244,254};
__constant__ int c_CUMNW[NGRAPH+1]= {0,8,16,25,33,41,50,58,67,75,83,91,99,107,116,124,132};

// fused Q|K projections in bf16, row m = rr*NNODES+node: b32-packed pairs,
// [RN][512] b32 (cols 0..255 = Q heads, 256..511 = K heads)
__device__ unsigned g_QKb[(size_t)RN * 512];   // 33 MB

// ---------------------------------------------------------------------------
// bf16 mma.sync helpers (sm_103 non-'a' safe)
// ---------------------------------------------------------------------------
__device__ __forceinline__ void mma_bf16(float* c, const unsigned* a,
                                         unsigned b0, unsigned b1) {
    asm volatile(
        "mma.sync.aligned.m16n8k16.row.col.f32.bf16.bf16.f32 "
        "{%0,%1,%2,%3}, {%4,%5,%6,%7}, {%8,%9}, {%0,%1,%2,%3};"
        : "+f"(c[0]), "+f"(c[1]), "+f"(c[2]), "+f"(c[3])
        : "r"(a[0]), "r"(a[1]), "r"(a[2]), "r"(a[3]), "r"(b0), "r"(b1));
}

__device__ __forceinline__ void bf16_split4(float4 v, uint2& hi, uint2& lo) {
    __nv_bfloat162 h0 = __float22bfloat162_rn(make_float2(v.x, v.y));
    __nv_bfloat162 h1 = __float22bfloat162_rn(make_float2(v.z, v.w));
    float2 f0 = __bfloat1622float2(h0);
    float2 f1 = __bfloat1622float2(h1);
    __nv_bfloat162 l0 = __float22bfloat162_rn(make_float2(v.x - f0.x, v.y - f0.y));
    __nv_bfloat162 l1 = __float22bfloat162_rn(make_float2(v.z - f1.x, v.w - f1.y));
    hi = make_uint2(*(unsigned*)&h0, *(unsigned*)&h1);
    lo = make_uint2(*(unsigned*)&l0, *(unsigned*)&l1);
}
__device__ __forceinline__ uint2 bf16_hi4(float4 v) {
    __nv_bfloat162 h0 = __float22bfloat162_rn(make_float2(v.x, v.y));
    __nv_bfloat162 h1 = __float22bfloat162_rn(make_float2(v.z, v.w));
    return make_uint2(*(unsigned*)&h0, *(unsigned*)&h1);
}
__device__ __forceinline__ unsigned pack_bf16(float x, float y) {
    __nv_bfloat162 p = __float22bfloat162_rn(make_float2(x, y));
    return *(unsigned*)&p;
}

// ---------------------------------------------------------------------------
// GEMM: 2-pass split bf16 mma.sync (measured-good R6/R7), epilogue now stores
// bf16 (halved store traffic; attn consumes bf16 directly for its own mma).
// Interleaved zeroing of the 260MB output rides the idle DRAM pipe.
// ---------------------------------------------------------------------------
#define KC 32
#define LDB 18   // row stride in b32 (16 packed bf16x2 + 2 pad)

__global__ __launch_bounds__(256) void gemm_kernel(
    const float* __restrict__ A,
    const float* __restrict__ Wq, const float* __restrict__ bq,
    const float* __restrict__ Wk, const float* __restrict__ bk,
    float* __restrict__ out)
{
    __shared__ unsigned Ah[128 * LDB];
    __shared__ unsigned Al[128 * LDB];
    __shared__ unsigned Bh[128 * LDB];

    const int bn  = blockIdx.x;
    const int bm  = blockIdx.y;
    const int m0  = bm * 128;
    const int n0g = bn * 128;
    const int bid = blockIdx.y * 8 + blockIdx.x;

    const float* B; const float* bias; int n0;
    if (n0g < 512) { B = Wq; bias = bq; n0 = n0g; }
    else           { B = Wk; bias = bk; n0 = n0g - 512; }

    const int tid  = threadIdx.x;
    const int warp = tid >> 5;
    const int lane = tid & 31;
    const int wm   = warp >> 1;
    const int wn   = warp & 1;
    const int grp  = lane >> 2;
    const int tig  = lane & 3;

    float4* const out4 = reinterpret_cast<float4*>(out);
    const size_t zstride = (size_t)1016 * 256;
    size_t zidx = (size_t)bid * 256 + tid;
    const float4 z4 = make_float4(0.f, 0.f, 0.f, 0.f);

    float acc[2][8][4];
#pragma unroll
    for (int mt = 0; mt < 2; mt++)
#pragma unroll
        for (int nt = 0; nt < 8; nt++)
#pragma unroll
            for (int i = 0; i < 4; i++) acc[mt][nt][i] = 0.f;

#pragma unroll 1
    for (int k0 = 0; k0 < FIN; k0 += KC) {
#pragma unroll
        for (int j = 0; j < 8; j++) {
            if (zidx < NOUT4) out4[zidx] = z4;
            zidx += zstride;
        }

#pragma unroll
        for (int it = 0; it < 4; it++) {
            const int idx = tid + it * 256;
            const int row = idx >> 3;
            const int c4  = (idx & 7) << 2;
            const int cb  = row * LDB + ((idx & 7) << 1);
            int gm = m0 + row; if (gm >= RN) gm = RN - 1;
            uint2 hi, lo;
            bf16_split4(*reinterpret_cast<const float4*>(A + (size_t)gm * FIN + k0 + c4), hi, lo);
            *reinterpret_cast<uint2*>(&Ah[cb]) = hi;
            *reinterpret_cast<uint2*>(&Al[cb]) = lo;
            *reinterpret_cast<uint2*>(&Bh[cb]) =
                bf16_hi4(*reinterpret_cast<const float4*>(B + (size_t)(n0 + row) * FIN + k0 + c4));
        }
        __syncthreads();

#pragma unroll
        for (int kb = 0; kb < KC / 2; kb += 8) {
            unsigned ah[2][4], al[2][4];
#pragma unroll
            for (int mt = 0; mt < 2; mt++) {
                const int r = (wm * 32 + mt * 16 + grp) * LDB + kb + tig;
                ah[mt][0] = Ah[r];
                ah[mt][1] = Ah[r + 8 * LDB];
                ah[mt][2] = Ah[r + 4];
                ah[mt][3] = Ah[r + 8 * LDB + 4];
                al[mt][0] = Al[r];
                al[mt][1] = Al[r + 8 * LDB];
                al[mt][2] = Al[r + 4];
                al[mt][3] = Al[r + 8 * LDB + 4];
            }
#pragma unroll
            for (int nt = 0; nt < 8; nt++) {
                const int nr = (wn * 64 + nt * 8 + grp) * LDB + kb + tig;
                const unsigned b0 = Bh[nr];
                const unsigned b1 = Bh[nr + 4];
#pragma unroll
                for (int mt = 0; mt < 2; mt++) {
                    mma_bf16(acc[mt][nt], ah[mt], b0, b1);
                    mma_bf16(acc[mt][nt], al[mt], b0, b1);
                }
            }
        }
        __syncthreads();
    }

    // epilogue: add bias, round to bf16, packed b32 stores
#pragma unroll
    for (int nt = 0; nt < 8; nt++) {
        const int cl = wn * 64 + nt * 8 + 2 * tig;       // even
        const float bx = bias[n0 + cl];
        const float by = bias[n0 + cl + 1];
        const int cb32 = (n0g + cl) >> 1;
#pragma unroll
        for (int mt = 0; mt < 2; mt++) {
            const int r0 = m0 + wm * 32 + mt * 16 + grp;
            if (r0 < RN)
                g_QKb[(size_t)r0 * 512 + cb32] = pack_bf16(acc[mt][nt][0] + bx, acc[mt][nt][1] + by);
            if (r0 + 8 < RN)
                g_QKb[(size_t)(r0 + 8) * 512 + cb32] = pack_bf16(acc[mt][nt][2] + bx, acc[mt][nt][3] + by);
        }
    }
}

// ---------------------------------------------------------------------------
// Attention via mma.sync: block = (window, relation, head-half). Per head:
// S[32,96] = Q Kt with bf16 HMMA (fragment patterns identical to gemm_kernel,
// validated R6/R7). Invalid nodes ZERO-FILLED in smem -> logits 0, exp 1,
// masked to 0 by hoisted column mask (no overflow/NaN path). Softmax rowsum:
// 8 threads/row + 3 shuffles. Per-thread fixed (row, 12-col) ownership keeps
// score accumulator in 12 registers across heads. Half-sums combined via
// atomicAdd (2 commutative adds/elem -> deterministic).
// ---------------------------------------------------------------------------
#define LDK 36    // tile row stride, b32 (32 data + 4 pad; conflict-free frags)
#define LDE 100   // Es row stride, floats

__global__ __launch_bounds__(256, 3) void attn_kernel(float* __restrict__ out)
{
    __shared__ unsigned Qs[32 * LDK];
    __shared__ unsigned Ks[96 * LDK];
    __shared__ float    Es[32 * LDE];
    __shared__ int      qn[32];
    __shared__ int      kn[96];

    const int wi  = blockIdx.x;
    const int rr  = blockIdx.y;
    const int hb  = blockIdx.z * 4;
    const int tid = threadIdx.x;

    int g = 0;
#pragma unroll
    for (int t = 1; t < NGRAPH; t++) g += (c_CUMNW[t] <= wi);
    const int pofs = (wi - c_CUMNW[g]) * 32;

    if (tid < 32) {
        const int k = pofs + tid;
        qn[tid] = (k < c_LEN[g]) ? c_CUML[g] + k : -1;
    } else if (tid < 128) {
        const int c = tid - 32;
        const int k = pofs - 32 + c;
        kn[c] = (k >= 0 && k < c_LEN[g]) ? c_CUML[g] + k : -1;
    }
    __syncthreads();

    const int warp = tid >> 5;
    const int lane = tid & 31;
    const int grp  = lane >> 2;
    const int tig  = lane & 3;
    const int mt   = warp >> 2;          // 0..1 : 16-row tile
    const int ntb  = (warp & 3) * 3;     // 3 n-tiles per warp

    // hoisted column masks for this thread's 6 columns
    float mk[3][2];
#pragma unroll
    for (int j = 0; j < 3; j++) {
        const int col = (ntb + j) * 8 + 2 * tig;
        mk[j][0] = (kn[col]     >= 0) ? 1.f : 0.f;
        mk[j][1] = (kn[col + 1] >= 0) ? 1.f : 0.f;
    }

    // rowsum/accumulate mapping: thread owns (srow, cols sseg*12..+11)
    const int srow = tid >> 3;
    const int sseg = tid & 7;

    const uint4* const qk4 = reinterpret_cast<const uint4*>(g_QKb);
    const size_t rbase = (size_t)rr * NNODES;    // node row offset for this rel
    const uint4 zz = make_uint4(0u, 0u, 0u, 0u);

    float acc[12];
#pragma unroll
    for (int j = 0; j < 12; j++) acc[j] = 0.f;

#pragma unroll 1
    for (int h4 = 0; h4 < 4; h4++) {
        const int h = hb + h4;
        __syncthreads();     // tiles+Es from previous head fully consumed

        // ---- load tiles (zero-fill invalid nodes) ----
        {   // Q: 32 rows x 8 uint4
            const int row = tid >> 3, u4 = tid & 7;
            const int node = qn[row];
            const uint4 v = (node >= 0)
                ? qk4[(rbase + node) * 128 + h * 8 + u4] : zz;
            *reinterpret_cast<uint4*>(&Qs[row * LDK + u4 * 4]) = v;
        }
#pragma unroll
        for (int it = 0; it < 3; it++) {   // K: 96 rows x 8 uint4
            const int idx = tid + it * 256;
            const int row = idx >> 3, u4 = idx & 7;
            const int node = kn[row];
            const uint4 v = (node >= 0)
                ? qk4[(rbase + node) * 128 + 64 + h * 8 + u4] : zz;
            *reinterpret_cast<uint4*>(&Ks[row * LDK + u4 * 4]) = v;
        }
        __syncthreads();

        // ---- S = Q Kt : 3 tiles (m16n8), k=64 in 4 k16 steps ----
        float c[3][4];
#pragma unroll
        for (int j = 0; j < 3; j++)
#pragma unroll
            for (int i = 0; i < 4; i++) c[j][i] = 0.f;

#pragma unroll
        for (int kb = 0; kb < 32; kb += 8) {
            unsigned a[4];
            const int ra = (mt * 16 + grp) * LDK + kb + tig;
            a[0] = Qs[ra];
            a[1] = Qs[ra + 8 * LDK];
            a[2] = Qs[ra + 4];
            a[3] = Qs[ra + 8 * LDK + 4];
#pragma unroll
            for (int j = 0; j < 3; j++) {
                const int rb = ((ntb + j) * 8 + grp) * LDK + kb + tig;
                mma_bf16(c[j], a, Ks[rb], Ks[rb + 4]);
            }
        }

        // ---- exp + mask -> Es ----
        const int erow = mt * 16 + grp;
#pragma unroll
        for (int j = 0; j < 3; j++) {
            const int col = (ntb + j) * 8 + 2 * tig;
            float2 e0 = make_float2(__expf(c[j][0] * 0.125f) * mk[j][0],
                                    __expf(c[j][1] * 0.125f) * mk[j][1]);
            float2 e1 = make_float2(__expf(c[j][2] * 0.125f) * mk[j][0],
                                    __expf(c[j][3] * 0.125f) * mk[j][1]);
            *reinterpret_cast<float2*>(&Es[erow * LDE + col])       = e0;
            *reinterpret_cast<float2*>(&Es[(erow + 8) * LDE + col]) = e1;
        }
        __syncthreads();

        // ---- row softmax sum (8 threads/row) + accumulate into registers ----
        const float* er = &Es[srow * LDE + sseg * 12];
        const float4 v0 = *reinterpret_cast<const float4*>(er);
        const float4 v1 = *reinterpret_cast<const float4*>(er + 4);
        const float4 v2 = *reinterpret_cast<const float4*>(er + 8);
        float s = ((v0.x + v0.y) + (v0.z + v0.w))
                + ((v1.x + v1.y) + (v1.z + v1.w))
                + ((v2.x + v2.y) + (v2.z + v2.w));
#pragma unroll
        for (int off = 1; off < 8; off <<= 1)
            s += __shfl_xor_sync(0xffffffffu, s, off);
        const float inv = __fdividef(1.f, s);
        acc[0] += v0.x * inv; acc[1]  += v0.y * inv; acc[2]  += v0.z * inv; acc[3]  += v0.w * inv;
        acc[4] += v1.x * inv; acc[5]  += v1.y * inv; acc[6]  += v1.z * inv; acc[7]  += v1.w * inv;
        acc[8] += v2.x * inv; acc[9]  += v2.y * inv; acc[10] += v2.z * inv; acc[11] += v2.w * inv;
    }

    // ---- scatter: 2 atomic adds per output element across the z-halves ----
    const int q = qn[srow];
    if (q >= 0) {
        float* rowp = out + (size_t)q * RN + (size_t)rr * NNODES;
#pragma unroll
        for (int j = 0; j < 12; j++) {
            const int k = kn[sseg * 12 + j];
            if (k >= 0) atomicAdd(rowp + k, acc[j] * 0.125f);
        }
    }
}

// ---------------------------------------------------------------------------
extern "C" void kernel_launch(void* const* d_in, const int* in_sizes, int n_in,
                              void* d_out, int out_size)
{
    const float* nf = (const float*)d_in[0];
    const float* Wq = (const float*)d_in[1];
    const float* bq = (const float*)d_in[2];
    const float* Wk = (const float*)d_in[3];
    const float* bk = (const float*)d_in[4];
    float* out = (float*)d_out;

    dim3 ggrid(8, (RN + 127) / 128);
    gemm_kernel<<<ggrid, 256>>>(nf, Wq, bq, Wk, bk, out);

    dim3 agrid(NWIN, RREL, 2);
    attn_kernel<<<agrid, 256>>>(out);
}

// round 9
// speedup vs baseline: 2.8961x; 1.1025x over previous
#include <cuda_runtime.h>
#include <cuda_bf16.h>
#include <cstdint>
#include <cstddef>

// ---------------------------------------------------------------------------
// Static problem geometry
// ---------------------------------------------------------------------------
#define NGRAPH   16
#define NNODES   4033
#define RREL     4
#define NHEAD    8
#define FIN      256
#define RN       16132
#define NWIN     132
#define NOUT4    16265089ULL     // (4033*16132)/4 float4s in the output

__constant__ int c_CUML[NGRAPH]   = {0,251,498,761,1016,1256,1514,1763,2023,2275,2520,2776,3026,3274,3535,3779};
__constant__ int c_LEN[NGRAPH]    = {251,247,263,255,240,258,249,260,252,245,256,250,248,261,244,254};
__constant__ int c_CUMNW[NGRAPH+1]= {0,8,16,25,33,41,50,58,67,75,83,91,99,107,116,124,132};

// fused Q|K projections in bf16, row m = rr*NNODES+node: b32-packed pairs,
// [RN][512] b32 (cols 0..255 = Q heads, 256..511 = K heads)
__device__ unsigned g_QKb[(size_t)RN * 512];   // 33 MB

// ---------------------------------------------------------------------------
// bf16 mma.sync helpers (sm_103 non-'a' safe)
// ---------------------------------------------------------------------------
__device__ __forceinline__ void mma_bf16(float* c, const unsigned* a,
                                         unsigned b0, unsigned b1) {
    asm volatile(
        "mma.sync.aligned.m16n8k16.row.col.f32.bf16.bf16.f32 "
        "{%0,%1,%2,%3}, {%4,%5,%6,%7}, {%8,%9}, {%0,%1,%2,%3};"
        : "+f"(c[0]), "+f"(c[1]), "+f"(c[2]), "+f"(c[3])
        : "r"(a[0]), "r"(a[1]), "r"(a[2]), "r"(a[3]), "r"(b0), "r"(b1));
}

__device__ __forceinline__ uint2 bf16_hi4(float4 v) {
    __nv_bfloat162 h0 = __float22bfloat162_rn(make_float2(v.x, v.y));
    __nv_bfloat162 h1 = __float22bfloat162_rn(make_float2(v.z, v.w));
    return make_uint2(*(unsigned*)&h0, *(unsigned*)&h1);
}
__device__ __forceinline__ unsigned pack_bf16(float x, float y) {
    __nv_bfloat162 p = __float22bfloat162_rn(make_float2(x, y));
    return *(unsigned*)&p;
}

// ---------------------------------------------------------------------------
// GEMM: C[RN,1024] = A[RN,256]*[Wq;Wk]^T + bias, SINGLE-pass bf16 mma.sync.
// Error model (measured): each bf16 rounding source ~1e-4 final rel_err;
// with A+B+QK-storage rounded, predicted ~1.8e-4 (threshold 1e-3).
// Block 128x128, kc=32, 256 threads (8 warps: 4m x 2n).
// Interleaved zeroing of the 260MB output rides the DRAM pipe.
// ---------------------------------------------------------------------------
#define KC 32
#define LDB 18   // row stride in b32 (16 packed bf16x2 + 2 pad)

__global__ __launch_bounds__(256) void gemm_kernel(
    const float* __restrict__ A,
    const float* __restrict__ Wq, const float* __restrict__ bq,
    const float* __restrict__ Wk, const float* __restrict__ bk,
    float* __restrict__ out)
{
    __shared__ unsigned Ah[128 * LDB];
    __shared__ unsigned Bh[128 * LDB];

    const int bn  = blockIdx.x;
    const int bm  = blockIdx.y;
    const int m0  = bm * 128;
    const int n0g = bn * 128;
    const int bid = blockIdx.y * 8 + blockIdx.x;

    const float* B; const float* bias; int n0;
    if (n0g < 512) { B = Wq; bias = bq; n0 = n0g; }
    else           { B = Wk; bias = bk; n0 = n0g - 512; }

    const int tid  = threadIdx.x;
    const int warp = tid >> 5;
    const int lane = tid & 31;
    const int wm   = warp >> 1;
    const int wn   = warp & 1;
    const int grp  = lane >> 2;
    const int tig  = lane & 3;

    float4* const out4 = reinterpret_cast<float4*>(out);
    const size_t zstride = (size_t)1016 * 256;
    size_t zidx = (size_t)bid * 256 + tid;
    const float4 z4 = make_float4(0.f, 0.f, 0.f, 0.f);

    float acc[2][8][4];
#pragma unroll
    for (int mt = 0; mt < 2; mt++)
#pragma unroll
        for (int nt = 0; nt < 8; nt++)
#pragma unroll
            for (int i = 0; i < 4; i++) acc[mt][nt][i] = 0.f;

#pragma unroll 1
    for (int k0 = 0; k0 < FIN; k0 += KC) {
        // interleaved output zeroing: 8 float4 per chunk (64 total >= 63 needed)
#pragma unroll
        for (int j = 0; j < 8; j++) {
            if (zidx < NOUT4) out4[zidx] = z4;
            zidx += zstride;
        }

        // cooperative tile load, rounded to bf16 once
#pragma unroll
        for (int it = 0; it < 4; it++) {
            const int idx = tid + it * 256;
            const int row = idx >> 3;
            const int c4  = (idx & 7) << 2;
            const int cb  = row * LDB + ((idx & 7) << 1);
            int gm = m0 + row; if (gm >= RN) gm = RN - 1;   // clamp (read-only dup)
            *reinterpret_cast<uint2*>(&Ah[cb]) =
                bf16_hi4(*reinterpret_cast<const float4*>(A + (size_t)gm * FIN + k0 + c4));
            *reinterpret_cast<uint2*>(&Bh[cb]) =
                bf16_hi4(*reinterpret_cast<const float4*>(B + (size_t)(n0 + row) * FIN + k0 + c4));
        }
        __syncthreads();

#pragma unroll
        for (int kb = 0; kb < KC / 2; kb += 8) {     // b32 units: k16 per step
            unsigned ah[2][4];
#pragma unroll
            for (int mt = 0; mt < 2; mt++) {
                const int r = (wm * 32 + mt * 16 + grp) * LDB + kb + tig;
                ah[mt][0] = Ah[r];
                ah[mt][1] = Ah[r + 8 * LDB];
                ah[mt][2] = Ah[r + 4];
                ah[mt][3] = Ah[r + 8 * LDB + 4];
            }
#pragma unroll
            for (int nt = 0; nt < 8; nt++) {
                const int nr = (wn * 64 + nt * 8 + grp) * LDB + kb + tig;
                const unsigned b0 = Bh[nr];
                const unsigned b1 = Bh[nr + 4];
#pragma unroll
                for (int mt = 0; mt < 2; mt++)
                    mma_bf16(acc[mt][nt], ah[mt], b0, b1);
            }
        }
        __syncthreads();
    }

    // epilogue: add bias, round to bf16, packed b32 stores
#pragma unroll
    for (int nt = 0; nt < 8; nt++) {
        const int cl = wn * 64 + nt * 8 + 2 * tig;       // even
        const float bx = bias[n0 + cl];
        const float by = bias[n0 + cl + 1];
        const int cb32 = (n0g + cl) >> 1;
#pragma unroll
        for (int mt = 0; mt < 2; mt++) {
            const int r0 = m0 + wm * 32 + mt * 16 + grp;
            if (r0 < RN)
                g_QKb[(size_t)r0 * 512 + cb32] = pack_bf16(acc[mt][nt][0] + bx, acc[mt][nt][1] + by);
            if (r0 + 8 < RN)
                g_QKb[(size_t)(r0 + 8) * 512 + cb32] = pack_bf16(acc[mt][nt][2] + bx, acc[mt][nt][3] + by);
        }
    }
}

// ---------------------------------------------------------------------------
// Attention via mma.sync (measured 45.7us R8, unchanged): block = (window,
// relation, head-half). Per head: S[32,96] = Q Kt bf16 HMMA; invalid nodes
// zero-filled -> exp(0)=1 masked to 0 by hoisted column mask. Row softmax via
// Es smem + 8-thread rowsum. Half-sums combined via atomicAdd (2 commutative
// adds/elem -> deterministic). Output pre-zeroed by gemm_kernel.
// ---------------------------------------------------------------------------
#define LDK 36    // tile row stride, b32 (32 data + 4 pad; conflict-free frags)
#define LDE 100   // Es row stride, floats

__global__ __launch_bounds__(256, 3) void attn_kernel(float* __restrict__ out)
{
    __shared__ unsigned Qs[32 * LDK];
    __shared__ unsigned Ks[96 * LDK];
    __shared__ float    Es[32 * LDE];
    __shared__ int      qn[32];
    __shared__ int      kn[96];

    const int wi  = blockIdx.x;
    const int rr  = blockIdx.y;
    const int hb  = blockIdx.z * 4;
    const int tid = threadIdx.x;

    int g = 0;
#pragma unroll
    for (int t = 1; t < NGRAPH; t++) g += (c_CUMNW[t] <= wi);
    const int pofs = (wi - c_CUMNW[g]) * 32;

    if (tid < 32) {
        const int k = pofs + tid;
        qn[tid] = (k < c_LEN[g]) ? c_CUML[g] + k : -1;
    } else if (tid < 128) {
        const int c = tid - 32;
        const int k = pofs - 32 + c;
        kn[c] = (k >= 0 && k < c_LEN[g]) ? c_CUML[g] + k : -1;
    }
    __syncthreads();

    const int warp = tid >> 5;
    const int lane = tid & 31;
    const int grp  = lane >> 2;
    const int tig  = lane & 3;
    const int mt   = warp >> 2;          // 0..1 : 16-row tile
    const int ntb  = (warp & 3) * 3;     // 3 n-tiles per warp

    // hoisted column masks for this thread's 6 columns
    float mk[3][2];
#pragma unroll
    for (int j = 0; j < 3; j++) {
        const int col = (ntb + j) * 8 + 2 * tig;
        mk[j][0] = (kn[col]     >= 0) ? 1.f : 0.f;
        mk[j][1] = (kn[col + 1] >= 0) ? 1.f : 0.f;
    }

    // rowsum/accumulate mapping: thread owns (srow, cols sseg*12..+11)
    const int srow = tid >> 3;
    const int sseg = tid & 7;

    const uint4* const qk4 = reinterpret_cast<const uint4*>(g_QKb);
    const size_t rbase = (size_t)rr * NNODES;
    const uint4 zz = make_uint4(0u, 0u, 0u, 0u);

    float acc[12];
#pragma unroll
    for (int j = 0; j < 12; j++) acc[j] = 0.f;

#pragma unroll 1
    for (int h4 = 0; h4 < 4; h4++) {
        const int h = hb + h4;
        __syncthreads();     // tiles+Es from previous head fully consumed

        {   // Q: 32 rows x 8 uint4
            const int row = tid >> 3, u4 = tid & 7;
            const int node = qn[row];
            const uint4 v = (node >= 0)
                ? qk4[(rbase + node) * 128 + h * 8 + u4] : zz;
            *reinterpret_cast<uint4*>(&Qs[row * LDK + u4 * 4]) = v;
        }
#pragma unroll
        for (int it = 0; it < 3; it++) {   // K: 96 rows x 8 uint4
            const int idx = tid + it * 256;
            const int row = idx >> 3, u4 = idx & 7;
            const int node = kn[row];
            const uint4 v = (node >= 0)
                ? qk4[(rbase + node) * 128 + 64 + h * 8 + u4] : zz;
            *reinterpret_cast<uint4*>(&Ks[row * LDK + u4 * 4]) = v;
        }
        __syncthreads();

        // ---- S = Q Kt : 3 tiles (m16n8), k=64 in 4 k16 steps ----
        float c[3][4];
#pragma unroll
        for (int j = 0; j < 3; j++)
#pragma unroll
            for (int i = 0; i < 4; i++) c[j][i] = 0.f;

#pragma unroll
        for (int kb = 0; kb < 32; kb += 8) {
            unsigned a[4];
            const int ra = (mt * 16 + grp) * LDK + kb + tig;
            a[0] = Qs[ra];
            a[1] = Qs[ra + 8 * LDK];
            a[2] = Qs[ra + 4];
            a[3] = Qs[ra + 8 * LDK + 4];
#pragma unroll
            for (int j = 0; j < 3; j++) {
                const int rb = ((ntb + j) * 8 + grp) * LDK + kb + tig;
                mma_bf16(c[j], a, Ks[rb], Ks[rb + 4]);
            }
        }

        // ---- exp + mask -> Es ----
        const int erow = mt * 16 + grp;
#pragma unroll
        for (int j = 0; j < 3; j++) {
            const int col = (ntb + j) * 8 + 2 * tig;
            float2 e0 = make_float2(__expf(c[j][0] * 0.125f) * mk[j][0],
                                    __expf(c[j][1] * 0.125f) * mk[j][1]);
            float2 e1 = make_float2(__expf(c[j][2] * 0.125f) * mk[j][0],
                                    __expf(c[j][3] * 0.125f) * mk[j][1]);
            *reinterpret_cast<float2*>(&Es[erow * LDE + col])       = e0;
            *reinterpret_cast<float2*>(&Es[(erow + 8) * LDE + col]) = e1;
        }
        __syncthreads();

        // ---- row softmax sum (8 threads/row) + accumulate into registers ----
        const float* er = &Es[srow * LDE + sseg * 12];
        const float4 v0 = *reinterpret_cast<const float4*>(er);
        const float4 v1 = *reinterpret_cast<const float4*>(er + 4);
        const float4 v2 = *reinterpret_cast<const float4*>(er + 8);
        float s = ((v0.x + v0.y) + (v0.z + v0.w))
                + ((v1.x + v1.y) + (v1.z + v1.w))
                + ((v2.x + v2.y) + (v2.z + v2.w));
#pragma unroll
        for (int off = 1; off < 8; off <<= 1)
            s += __shfl_xor_sync(0xffffffffu, s, off);
        const float inv = __fdividef(1.f, s);
        acc[0] += v0.x * inv; acc[1]  += v0.y * inv; acc[2]  += v0.z * inv; acc[3]  += v0.w * inv;
        acc[4] += v1.x * inv; acc[5]  += v1.y * inv; acc[6]  += v1.z * inv; acc[7]  += v1.w * inv;
        acc[8] += v2.x * inv; acc[9]  += v2.y * inv; acc[10] += v2.z * inv; acc[11] += v2.w * inv;
    }

    // ---- scatter: 2 atomic adds per output element across the z-halves ----
    const int q = qn[srow];
    if (q >= 0) {
        float* rowp = out + (size_t)q * RN + (size_t)rr * NNODES;
#pragma unroll
        for (int j = 0; j < 12; j++) {
            const int k = kn[sseg * 12 + j];
            if (k >= 0) atomicAdd(rowp + k, acc[j] * 0.125f);
        }
    }
}

// ---------------------------------------------------------------------------
extern "C" void kernel_launch(void* const* d_in, const int* in_sizes, int n_in,
                              void* d_out, int out_size)
{
    const float* nf = (const float*)d_in[0];
    const float* Wq = (const float*)d_in[1];
    const float* bq = (const float*)d_in[2];
    const float* Wk = (const float*)d_in[3];
    const float* bk = (const float*)d_in[4];
    float* out = (float*)d_out;

    dim3 ggrid(8, (RN + 127) / 128);
    gemm_kernel<<<ggrid, 256>>>(nf, Wq, bq, Wk, bk, out);

    dim3 agrid(NWIN, RREL, 2);
    attn_kernel<<<agrid, 256>>>(out);
}

// round 10
// speedup vs baseline: 3.4007x; 1.1742x over previous
#include <cuda_runtime.h>
#include <cuda_bf16.h>
#include <cstdint>
#include <cstddef>

// ---------------------------------------------------------------------------
// Static problem geometry
// ---------------------------------------------------------------------------
#define NGRAPH   16
#define NNODES   4033
#define RREL     4
#define NHEAD    8
#define FIN      256
#define RN       16132
#define NWIN     132
#define NOUT4    16265089ULL     // (4033*16132)/4 float4s in the output

__constant__ int c_CUML[NGRAPH]   = {0,251,498,761,1016,1256,1514,1763,2023,2275,2520,2776,3026,3274,3535,3779};
__constant__ int c_LEN[NGRAPH]    = {251,247,263,255,240,258,249,260,252,245,256,250,248,261,244,254};
__constant__ int c_CUMNW[NGRAPH+1]= {0,8,16,25,33,41,50,58,67,75,83,91,99,107,116,124,132};

// fused Q|K projections in bf16, row m = rr*NNODES+node: b32-packed pairs,
// [RN][512] b32 (cols 0..255 = Q heads, 256..511 = K heads)
__device__ unsigned g_QKb[(size_t)RN * 512];   // 33 MB

// ---------------------------------------------------------------------------
// helpers
// ---------------------------------------------------------------------------
__device__ __forceinline__ void mma_bf16(float* c, const unsigned* a,
                                         unsigned b0, unsigned b1) {
    asm volatile(
        "mma.sync.aligned.m16n8k16.row.col.f32.bf16.bf16.f32 "
        "{%0,%1,%2,%3}, {%4,%5,%6,%7}, {%8,%9}, {%0,%1,%2,%3};"
        : "+f"(c[0]), "+f"(c[1]), "+f"(c[2]), "+f"(c[3])
        : "r"(a[0]), "r"(a[1]), "r"(a[2]), "r"(a[3]), "r"(b0), "r"(b1));
}
__device__ __forceinline__ uint2 bf16_hi4(float4 v) {
    __nv_bfloat162 h0 = __float22bfloat162_rn(make_float2(v.x, v.y));
    __nv_bfloat162 h1 = __float22bfloat162_rn(make_float2(v.z, v.w));
    return make_uint2(*(unsigned*)&h0, *(unsigned*)&h1);
}
__device__ __forceinline__ unsigned pack_bf16(float x, float y) {
    __nv_bfloat162 p = __float22bfloat162_rn(make_float2(x, y));
    return *(unsigned*)&p;
}
__device__ __forceinline__ uint32_t smem_u32(const void* p) {
    uint32_t a;
    asm("{ .reg .u64 t; cvta.to.shared.u64 t, %1; cvt.u32.u64 %0, t; }" : "=r"(a) : "l"(p));
    return a;
}
__device__ __forceinline__ void cp_async16(uint32_t dst, const void* src) {
    asm volatile("cp.async.cg.shared.global [%0], [%1], 16;" :: "r"(dst), "l"(src) : "memory");
}

// ---------------------------------------------------------------------------
// GEMM: C[RN,1024] = A[RN,256]*[Wq;Wk]^T + bias, single-pass bf16 mma.sync
// (error model measured: ~1.5e-4 final). Block 128x128, kc=32, 8 warps.
// Interleaved zeroing of the 260MB output. NEW: epilogue stages fragments in
// smem (bank-conflict-free stride 68) then stores coalesced STG.128 —
// removes the ~4x sector waste of scattered STG.32 bf16 stores.
// ---------------------------------------------------------------------------
#define KC 32
#define LDB 18   // mainloop row stride in b32 (16 packed bf16x2 + 2 pad)

__global__ __launch_bounds__(256) void gemm_kernel(
    const float* __restrict__ A,
    const float* __restrict__ Wq, const float* __restrict__ bq,
    const float* __restrict__ Wk, const float* __restrict__ bk,
    float* __restrict__ out)
{
    __shared__ __align__(16) unsigned smem_u[128 * 68];   // 34.8 KB (union)
    unsigned* const Ah = smem_u;                // 128*18
    unsigned* const Bh = smem_u + 128 * LDB;    // 128*18

    const int bn  = blockIdx.x;
    const int bm  = blockIdx.y;
    const int m0  = bm * 128;
    const int n0g = bn * 128;
    const int bid = blockIdx.y * 8 + blockIdx.x;

    const float* B; const float* bias; int n0;
    if (n0g < 512) { B = Wq; bias = bq; n0 = n0g; }
    else           { B = Wk; bias = bk; n0 = n0g - 512; }

    const int tid  = threadIdx.x;
    const int warp = tid >> 5;
    const int lane = tid & 31;
    const int wm   = warp >> 1;
    const int wn   = warp & 1;
    const int grp  = lane >> 2;
    const int tig  = lane & 3;

    float4* const out4 = reinterpret_cast<float4*>(out);
    const size_t zstride = (size_t)1016 * 256;
    size_t zidx = (size_t)bid * 256 + tid;
    const float4 z4 = make_float4(0.f, 0.f, 0.f, 0.f);

    float acc[2][8][4];
#pragma unroll
    for (int mt = 0; mt < 2; mt++)
#pragma unroll
        for (int nt = 0; nt < 8; nt++)
#pragma unroll
            for (int i = 0; i < 4; i++) acc[mt][nt][i] = 0.f;

#pragma unroll 1
    for (int k0 = 0; k0 < FIN; k0 += KC) {
        // interleaved output zeroing: 8 float4 per chunk (64 total >= 63 needed)
#pragma unroll
        for (int j = 0; j < 8; j++) {
            if (zidx < NOUT4) out4[zidx] = z4;
            zidx += zstride;
        }

        // cooperative tile load, rounded to bf16 once
#pragma unroll
        for (int it = 0; it < 4; it++) {
            const int idx = tid + it * 256;
            const int row = idx >> 3;
            const int c4  = (idx & 7) << 2;
            const int cb  = row * LDB + ((idx & 7) << 1);
            int gm = m0 + row; if (gm >= RN) gm = RN - 1;   // clamp (read-only dup)
            *reinterpret_cast<uint2*>(&Ah[cb]) =
                bf16_hi4(*reinterpret_cast<const float4*>(A + (size_t)gm * FIN + k0 + c4));
            *reinterpret_cast<uint2*>(&Bh[cb]) =
                bf16_hi4(*reinterpret_cast<const float4*>(B + (size_t)(n0 + row) * FIN + k0 + c4));
        }
        __syncthreads();

#pragma unroll
        for (int kb = 0; kb < KC / 2; kb += 8) {     // b32 units: k16 per step
            unsigned ah[2][4];
#pragma unroll
            for (int mt = 0; mt < 2; mt++) {
                const int r = (wm * 32 + mt * 16 + grp) * LDB + kb + tig;
                ah[mt][0] = Ah[r];
                ah[mt][1] = Ah[r + 8 * LDB];
                ah[mt][2] = Ah[r + 4];
                ah[mt][3] = Ah[r + 8 * LDB + 4];
            }
#pragma unroll
            for (int nt = 0; nt < 8; nt++) {
                const int nr = (wn * 64 + nt * 8 + grp) * LDB + kb + tig;
                const unsigned b0 = Bh[nr];
                const unsigned b1 = Bh[nr + 4];
#pragma unroll
                for (int mt = 0; mt < 2; mt++)
                    mma_bf16(acc[mt][nt], ah[mt], b0, b1);
            }
        }
        __syncthreads();
    }

    // ---- epilogue: bias + bf16 pack -> smem stage (stride 68: banks
    // 4*grp+tig, conflict-free) -> coalesced uint4 stores ----
    unsigned* const stage = smem_u;
#pragma unroll
    for (int nt = 0; nt < 8; nt++) {
        const int cl = wn * 64 + nt * 8 + 2 * tig;
        const float bx = bias[n0 + cl];
        const float by = bias[n0 + cl + 1];
        const int colb = wn * 32 + nt * 4 + tig;
#pragma unroll
        for (int mt = 0; mt < 2; mt++) {
            const int rl = wm * 32 + mt * 16 + grp;
            stage[rl * 68 + colb]       = pack_bf16(acc[mt][nt][0] + bx, acc[mt][nt][1] + by);
            stage[(rl + 8) * 68 + colb] = pack_bf16(acc[mt][nt][2] + bx, acc[mt][nt][3] + by);
        }
    }
    __syncthreads();
#pragma unroll
    for (int i = 0; i < 8; i++) {
        const int idx = tid + i * 256;
        const int row = idx >> 4;          // 16 uint4 per 64-b32 row
        const int u4  = idx & 15;
        const int gmr = m0 + row;
        if (gmr < RN)
            *reinterpret_cast<uint4*>(g_QKb + (size_t)gmr * 512 + (n0g >> 1) + u4 * 4) =
                *reinterpret_cast<const uint4*>(stage + row * 68 + u4 * 4);
    }
}

// ---------------------------------------------------------------------------
// Attention via mma.sync + cp.async double buffering: block = (window, rel,
// head-half). Invalid rows pre-zeroed ONCE in both buffers (cp.async skips
// them -> stay zero; exp(0)=1 masked to 0, no NaN path). Softmax in
// registers: per-warp quad-shuffle partial rowsums -> Ps[32][4] smem -> inv.
// Half-sums combined via atomicAdd (2 commutative adds/elem -> determin.).
// Output pre-zeroed by gemm_kernel.
// ---------------------------------------------------------------------------
#define LDK 36    // tile row stride, b32 (32 data + 4 pad; conflict-free frags)

__global__ __launch_bounds__(256, 3) void attn_kernel(float* __restrict__ out)
{
    __shared__ __align__(16) unsigned Qs[2][32 * LDK];   //  9.2 KB
    __shared__ __align__(16) unsigned Ks[2][96 * LDK];   // 27.6 KB
    __shared__ float Ps[32][4];
    __shared__ int   qn[32];
    __shared__ int   kn[96];

    const int wi  = blockIdx.x;
    const int rr  = blockIdx.y;
    const int hb  = blockIdx.z * 4;
    const int tid = threadIdx.x;

    int g = 0;
#pragma unroll
    for (int t = 1; t < NGRAPH; t++) g += (c_CUMNW[t] <= wi);
    const int pofs = (wi - c_CUMNW[g]) * 32;

    if (tid < 32) {
        const int k = pofs + tid;
        qn[tid] = (k < c_LEN[g]) ? c_CUML[g] + k : -1;
    } else if (tid < 128) {
        const int c = tid - 32;
        const int k = pofs - 32 + c;
        kn[c] = (k >= 0 && k < c_LEN[g]) ? c_CUML[g] + k : -1;
    }

    // zero both tile buffers (invalid rows stay zero forever)
    const uint4 zz = make_uint4(0u, 0u, 0u, 0u);
#pragma unroll
    for (int i = 0; i < 3; i++) {
        const int idx = tid + i * 256;
        if (idx < 576) reinterpret_cast<uint4*>(Qs)[idx] = zz;
    }
#pragma unroll
    for (int i = 0; i < 7; i++) {
        const int idx = tid + i * 256;
        if (idx < 1728) reinterpret_cast<uint4*>(Ks)[idx] = zz;
    }
    __syncthreads();      // qn/kn + zeros visible

    const int warp = tid >> 5;
    const int lane = tid & 31;
    const int grp  = lane >> 2;
    const int tig  = lane & 3;
    const int mt   = warp >> 2;          // 0..1 : 16-row tile
    const int nw   = warp & 3;           // n-warp index
    const int ntb  = nw * 3;             // 3 n-tiles per warp
    const int row0 = mt * 16 + grp;
    const int row1 = row0 + 8;

    float mk[3][2];
#pragma unroll
    for (int j = 0; j < 3; j++) {
        const int col = (ntb + j) * 8 + 2 * tig;
        mk[j][0] = (kn[col]     >= 0) ? 1.f : 0.f;
        mk[j][1] = (kn[col + 1] >= 0) ? 1.f : 0.f;
    }

    const uint4* const qk4 = reinterpret_cast<const uint4*>(g_QKb);
    const size_t rbase = (size_t)rr * NNODES;
    const uint32_t qsb[2] = { smem_u32(&Qs[0][0]), smem_u32(&Qs[1][0]) };
    const uint32_t ksb[2] = { smem_u32(&Ks[0][0]), smem_u32(&Ks[1][0]) };

    // async tile loader: valid rows only (invalid stay zero)
    auto load_head = [&](int h, int b) {
        {
            const int row = tid >> 3, u4 = tid & 7;
            const int node = qn[row];
            if (node >= 0)
                cp_async16(qsb[b] + (row * LDK + u4 * 4) * 4,
                           qk4 + (rbase + node) * 128 + h * 8 + u4);
        }
#pragma unroll
        for (int it = 0; it < 3; it++) {
            const int idx = tid + it * 256;
            const int row = idx >> 3, u4 = idx & 7;
            const int node = kn[row];
            if (node >= 0)
                cp_async16(ksb[b] + (row * LDK + u4 * 4) * 4,
                           qk4 + (rbase + node) * 128 + 64 + h * 8 + u4);
        }
        asm volatile("cp.async.commit_group;" ::: "memory");
    };

    float acc[3][4];
#pragma unroll
    for (int j = 0; j < 3; j++)
#pragma unroll
        for (int i = 0; i < 4; i++) acc[j][i] = 0.f;

    load_head(hb, 0);

#pragma unroll 1
    for (int h4 = 0; h4 < 4; h4++) {
        const int b = h4 & 1;
        if (h4 < 3) {
            load_head(hb + h4 + 1, b ^ 1);
            asm volatile("cp.async.wait_group 1;" ::: "memory");
        } else {
            asm volatile("cp.async.wait_group 0;" ::: "memory");
        }
        __syncthreads();     // buffer b complete block-wide; Ps consumed

        // ---- S = Q Kt : 3 m16n8 tiles, k=64 in 4 k16 steps ----
        float c[3][4];
#pragma unroll
        for (int j = 0; j < 3; j++)
#pragma unroll
            for (int i = 0; i < 4; i++) c[j][i] = 0.f;

        const unsigned* Qb = &Qs[b][0];
        const unsigned* Kb = &Ks[b][0];
#pragma unroll
        for (int kb = 0; kb < 32; kb += 8) {
            unsigned a[4];
            const int ra = row0 * LDK + kb + tig;
            a[0] = Qb[ra];
            a[1] = Qb[ra + 8 * LDK];
            a[2] = Qb[ra + 4];
            a[3] = Qb[ra + 8 * LDK + 4];
#pragma unroll
            for (int j = 0; j < 3; j++) {
                const int rb = ((ntb + j) * 8 + grp) * LDK + kb + tig;
                mma_bf16(c[j], a, Kb[rb], Kb[rb + 4]);
            }
        }

        // ---- exp + mask (registers) ----
        float e[3][4];
#pragma unroll
        for (int j = 0; j < 3; j++) {
            e[j][0] = __expf(c[j][0] * 0.125f) * mk[j][0];
            e[j][1] = __expf(c[j][1] * 0.125f) * mk[j][1];
            e[j][2] = __expf(c[j][2] * 0.125f) * mk[j][0];
            e[j][3] = __expf(c[j][3] * 0.125f) * mk[j][1];
        }

        // ---- row sums: quad shuffle -> per-warp partial -> Ps ----
        float p0 = (e[0][0] + e[0][1]) + (e[1][0] + e[1][1]) + (e[2][0] + e[2][1]);
        float p1 = (e[0][2] + e[0][3]) + (e[1][2] + e[1][3]) + (e[2][2] + e[2][3]);
        p0 += __shfl_xor_sync(0xffffffffu, p0, 1);
        p0 += __shfl_xor_sync(0xffffffffu, p0, 2);
        p1 += __shfl_xor_sync(0xffffffffu, p1, 1);
        p1 += __shfl_xor_sync(0xffffffffu, p1, 2);
        if (tig == 0) {
            Ps[row0][nw] = p0;
            Ps[row1][nw] = p1;
        }
        __syncthreads();

        const float4 s0 = *reinterpret_cast<const float4*>(Ps[row0]);
        const float4 s1 = *reinterpret_cast<const float4*>(Ps[row1]);
        const float inv0 = __fdividef(1.f, (s0.x + s0.y) + (s0.z + s0.w));
        const float inv1 = __fdividef(1.f, (s1.x + s1.y) + (s1.z + s1.w));
#pragma unroll
        for (int j = 0; j < 3; j++) {
            acc[j][0] += e[j][0] * inv0;
            acc[j][1] += e[j][1] * inv0;
            acc[j][2] += e[j][2] * inv1;
            acc[j][3] += e[j][3] * inv1;
        }
    }

    // ---- scatter: 2 atomic adds per output element across the z-halves ----
    const int q0 = qn[row0];
    const int q1 = qn[row1];
#pragma unroll
    for (int j = 0; j < 3; j++) {
        const int col = (ntb + j) * 8 + 2 * tig;
        const int k0 = kn[col], k1 = kn[col + 1];
        if (q0 >= 0) {
            float* rp = out + (size_t)q0 * RN + rbase;
            if (k0 >= 0) atomicAdd(rp + k0, acc[j][0] * 0.125f);
            if (k1 >= 0) atomicAdd(rp + k1, acc[j][1] * 0.125f);
        }
        if (q1 >= 0) {
            float* rp = out + (size_t)q1 * RN + rbase;
            if (k0 >= 0) atomicAdd(rp + k0, acc[j][2] * 0.125f);
            if (k1 >= 0) atomicAdd(rp + k1, acc[j][3] * 0.125f);
        }
    }
}

// ---------------------------------------------------------------------------
extern "C" void kernel_launch(void* const* d_in, const int* in_sizes, int n_in,
                              void* d_out, int out_size)
{
    const float* nf = (const float*)d_in[0];
    const float* Wq = (const float*)d_in[1];
    const float* bq = (const float*)d_in[2];
    const float* Wk = (const float*)d_in[3];
    const float* bk = (const float*)d_in[4];
    float* out = (float*)d_out;

    dim3 ggrid(8, (RN + 127) / 128);
    gemm_kernel<<<ggrid, 256>>>(nf, Wq, bq, Wk, bk, out);

    dim3 agrid(NWIN, RREL, 2);
    attn_kernel<<<agrid, 256>>>(out);
}

// round 11
// speedup vs baseline: 3.7589x; 1.1053x over previous
#include <cuda_runtime.h>
#include <cuda_bf16.h>
#include <cstdint>
#include <cstddef>

// ---------------------------------------------------------------------------
// Static problem geometry
// ---------------------------------------------------------------------------
#define NGRAPH   16
#define NNODES   4033
#define RREL     4
#define NHEAD    8
#define FIN      256
#define RN       16132
#define NWIN     132
#define NOUT4    16265089ULL     // (4033*16132)/4 float4s in the output

__constant__ int c_CUML[NGRAPH]   = {0,251,498,761,1016,1256,1514,1763,2023,2275,2520,2776,3026,3274,3535,3779};
__constant__ int c_LEN[NGRAPH]    = {251,247,263,255,240,258,249,260,252,245,256,250,248,261,244,254};
__constant__ int c_CUMNW[NGRAPH+1]= {0,8,16,25,33,41,50,58,67,75,83,91,99,107,116,124,132};

// fused Q|K projections in bf16, row m = rr*NNODES+node: b32-packed pairs,
// [RN][512] b32 (cols 0..255 = Q heads, 256..511 = K heads)
__device__ unsigned g_QKb[(size_t)RN * 512];   // 33 MB

// ---------------------------------------------------------------------------
// helpers
// ---------------------------------------------------------------------------
__device__ __forceinline__ void mma_bf16(float* c, const unsigned* a,
                                         unsigned b0, unsigned b1) {
    asm volatile(
        "mma.sync.aligned.m16n8k16.row.col.f32.bf16.bf16.f32 "
        "{%0,%1,%2,%3}, {%4,%5,%6,%7}, {%8,%9}, {%0,%1,%2,%3};"
        : "+f"(c[0]), "+f"(c[1]), "+f"(c[2]), "+f"(c[3])
        : "r"(a[0]), "r"(a[1]), "r"(a[2]), "r"(a[3]), "r"(b0), "r"(b1));
}
__device__ __forceinline__ uint2 bf16_hi4(float4 v) {
    __nv_bfloat162 h0 = __float22bfloat162_rn(make_float2(v.x, v.y));
    __nv_bfloat162 h1 = __float22bfloat162_rn(make_float2(v.z, v.w));
    return make_uint2(*(unsigned*)&h0, *(unsigned*)&h1);
}
__device__ __forceinline__ unsigned pack_bf16(float x, float y) {
    __nv_bfloat162 p = __float22bfloat162_rn(make_float2(x, y));
    return *(unsigned*)&p;
}
__device__ __forceinline__ uint32_t smem_u32(const void* p) {
    uint32_t a;
    asm("{ .reg .u64 t; cvta.to.shared.u64 t, %1; cvt.u32.u64 %0, t; }" : "=r"(a) : "l"(p));
    return a;
}
__device__ __forceinline__ void cp_async16(uint32_t dst, const void* src) {
    asm volatile("cp.async.cg.shared.global [%0], [%1], 16;" :: "r"(dst), "l"(src) : "memory");
}

// ---------------------------------------------------------------------------
// GEMM: C[RN,1024] = A[RN,256]*[Wq;Wk]^T + bias, single-pass bf16 mma.sync.
// Software-pipelined: chunk c+1's global loads (register-staged) are issued
// before chunk c's MMA loop, hiding L2/DRAM latency behind tensor work.
// __launch_bounds__(256,2) forces <=128 regs -> 2 CTAs/SM for cross-block
// overlap. Interleaved zeroing of the 260MB output rides the DRAM pipe.
// ---------------------------------------------------------------------------
#define KC 32
#define LDB 18   // mainloop row stride in b32 (16 packed bf16x2 + 2 pad)

__global__ __launch_bounds__(256, 2) void gemm_kernel(
    const float* __restrict__ A,
    const float* __restrict__ Wq, const float* __restrict__ bq,
    const float* __restrict__ Wk, const float* __restrict__ bk,
    float* __restrict__ out)
{
    __shared__ __align__(16) unsigned smem_u[128 * 68];   // 34.8 KB (union)
    unsigned* const Ah = smem_u;                // 128*18
    unsigned* const Bh = smem_u + 128 * LDB;    // 128*18

    const int bn  = blockIdx.x;
    const int bm  = blockIdx.y;
    const int m0  = bm * 128;
    const int n0g = bn * 128;
    const int bid = blockIdx.y * 8 + blockIdx.x;

    const float* B; const float* bias; int n0;
    if (n0g < 512) { B = Wq; bias = bq; n0 = n0g; }
    else           { B = Wk; bias = bk; n0 = n0g - 512; }

    const int tid  = threadIdx.x;
    const int warp = tid >> 5;
    const int lane = tid & 31;
    const int wm   = warp >> 1;
    const int wn   = warp & 1;
    const int grp  = lane >> 2;
    const int tig  = lane & 3;

    float4* const out4 = reinterpret_cast<float4*>(out);
    const size_t zstride = (size_t)1016 * 256;
    size_t zidx = (size_t)bid * 256 + tid;
    const float4 z4 = make_float4(0.f, 0.f, 0.f, 0.f);

    // per-thread load mapping: 4 (row, col4) pairs, fixed across chunks
    int arow[4]; int acol[4];
#pragma unroll
    for (int it = 0; it < 4; it++) {
        const int idx = tid + it * 256;
        arow[it] = idx >> 3;
        acol[it] = (idx & 7) << 2;
    }

    float acc[2][8][4];
#pragma unroll
    for (int mt = 0; mt < 2; mt++)
#pragma unroll
        for (int nt = 0; nt < 8; nt++)
#pragma unroll
            for (int i = 0; i < 4; i++) acc[mt][nt][i] = 0.f;

    // ---- prologue: load chunk 0 into registers ----
    float4 av[4], bv[4];
#pragma unroll
    for (int it = 0; it < 4; it++) {
        int gm = m0 + arow[it]; if (gm >= RN) gm = RN - 1;
        av[it] = *reinterpret_cast<const float4*>(A + (size_t)gm * FIN + acol[it]);
        bv[it] = *reinterpret_cast<const float4*>(B + (size_t)(n0 + arow[it]) * FIN + acol[it]);
    }

#pragma unroll 1
    for (int c = 0; c < FIN / KC; c++) {
        __syncthreads();             // previous chunk's smem fully consumed

        // convert + store staged registers to smem
#pragma unroll
        for (int it = 0; it < 4; it++) {
            const int cb = arow[it] * LDB + (acol[it] >> 1);
            *reinterpret_cast<uint2*>(&Ah[cb]) = bf16_hi4(av[it]);
            *reinterpret_cast<uint2*>(&Bh[cb]) = bf16_hi4(bv[it]);
        }

        // interleaved output zeroing: 8 float4 per chunk (64 total >= 63 needed)
#pragma unroll
        for (int j = 0; j < 8; j++) {
            if (zidx < NOUT4) out4[zidx] = z4;
            zidx += zstride;
        }
        __syncthreads();

        // issue next chunk's loads (latency hidden behind MMA loop below)
        if (c + 1 < FIN / KC) {
            const int k0n = (c + 1) * KC;
#pragma unroll
            for (int it = 0; it < 4; it++) {
                int gm = m0 + arow[it]; if (gm >= RN) gm = RN - 1;
                av[it] = *reinterpret_cast<const float4*>(A + (size_t)gm * FIN + k0n + acol[it]);
                bv[it] = *reinterpret_cast<const float4*>(B + (size_t)(n0 + arow[it]) * FIN + k0n + acol[it]);
            }
        }

        // ---- MMA loop over this chunk ----
#pragma unroll
        for (int kb = 0; kb < KC / 2; kb += 8) {     // b32 units: k16 per step
            unsigned ah[2][4];
#pragma unroll
            for (int mt = 0; mt < 2; mt++) {
                const int r = (wm * 32 + mt * 16 + grp) * LDB + kb + tig;
                ah[mt][0] = Ah[r];
                ah[mt][1] = Ah[r + 8 * LDB];
                ah[mt][2] = Ah[r + 4];
                ah[mt][3] = Ah[r + 8 * LDB + 4];
            }
#pragma unroll
            for (int nt = 0; nt < 8; nt++) {
                const int nr = (wn * 64 + nt * 8 + grp) * LDB + kb + tig;
                const unsigned b0 = Bh[nr];
                const unsigned b1 = Bh[nr + 4];
#pragma unroll
                for (int mt = 0; mt < 2; mt++)
                    mma_bf16(acc[mt][nt], ah[mt], b0, b1);
            }
        }
    }
    __syncthreads();

    // ---- epilogue: bias + bf16 pack -> smem stage -> coalesced uint4 stores ----
    unsigned* const stage = smem_u;
#pragma unroll
    for (int nt = 0; nt < 8; nt++) {
        const int cl = wn * 64 + nt * 8 + 2 * tig;
        const float bx = bias[n0 + cl];
        const float by = bias[n0 + cl + 1];
        const int colb = wn * 32 + nt * 4 + tig;
#pragma unroll
        for (int mt = 0; mt < 2; mt++) {
            const int rl = wm * 32 + mt * 16 + grp;
            stage[rl * 68 + colb]       = pack_bf16(acc[mt][nt][0] + bx, acc[mt][nt][1] + by);
            stage[(rl + 8) * 68 + colb] = pack_bf16(acc[mt][nt][2] + bx, acc[mt][nt][3] + by);
        }
    }
    __syncthreads();
#pragma unroll
    for (int i = 0; i < 8; i++) {
        const int idx = tid + i * 256;
        const int row = idx >> 4;          // 16 uint4 per 64-b32 row
        const int u4  = idx & 15;
        const int gmr = m0 + row;
        if (gmr < RN)
            *reinterpret_cast<uint4*>(g_QKb + (size_t)gmr * 512 + (n0g >> 1) + u4 * 4) =
                *reinterpret_cast<const uint4*>(stage + row * 68 + u4 * 4);
    }
}

// ---------------------------------------------------------------------------
// Attention via mma.sync + cp.async double buffering (measured 26.4us R10,
// unchanged): block = (window, rel, head-half). Invalid rows pre-zeroed once;
// exp(0)=1 masked to 0. Register softmax with Ps[32][4] partial rowsums.
// Half-sums combined via atomicAdd (2 commutative adds/elem -> determin.).
// Output pre-zeroed by gemm_kernel.
// ---------------------------------------------------------------------------
#define LDK 36    // tile row stride, b32 (32 data + 4 pad; conflict-free frags)

__global__ __launch_bounds__(256, 3) void attn_kernel(float* __restrict__ out)
{
    __shared__ __align__(16) unsigned Qs[2][32 * LDK];
    __shared__ __align__(16) unsigned Ks[2][96 * LDK];
    __shared__ float Ps[32][4];
    __shared__ int   qn[32];
    __shared__ int   kn[96];

    const int wi  = blockIdx.x;
    const int rr  = blockIdx.y;
    const int hb  = blockIdx.z * 4;
    const int tid = threadIdx.x;

    int g = 0;
#pragma unroll
    for (int t = 1; t < NGRAPH; t++) g += (c_CUMNW[t] <= wi);
    const int pofs = (wi - c_CUMNW[g]) * 32;

    if (tid < 32) {
        const int k = pofs + tid;
        qn[tid] = (k < c_LEN[g]) ? c_CUML[g] + k : -1;
    } else if (tid < 128) {
        const int c = tid - 32;
        const int k = pofs - 32 + c;
        kn[c] = (k >= 0 && k < c_LEN[g]) ? c_CUML[g] + k : -1;
    }

    const uint4 zz = make_uint4(0u, 0u, 0u, 0u);
#pragma unroll
    for (int i = 0; i < 3; i++) {
        const int idx = tid + i * 256;
        if (idx < 576) reinterpret_cast<uint4*>(Qs)[idx] = zz;
    }
#pragma unroll
    for (int i = 0; i < 7; i++) {
        const int idx = tid + i * 256;
        if (idx < 1728) reinterpret_cast<uint4*>(Ks)[idx] = zz;
    }
    __syncthreads();

    const int warp = tid >> 5;
    const int lane = tid & 31;
    const int grp  = lane >> 2;
    const int tig  = lane & 3;
    const int mt   = warp >> 2;
    const int nw   = warp & 3;
    const int ntb  = nw * 3;
    const int row0 = mt * 16 + grp;
    const int row1 = row0 + 8;

    float mk[3][2];
#pragma unroll
    for (int j = 0; j < 3; j++) {
        const int col = (ntb + j) * 8 + 2 * tig;
        mk[j][0] = (kn[col]     >= 0) ? 1.f : 0.f;
        mk[j][1] = (kn[col + 1] >= 0) ? 1.f : 0.f;
    }

    const uint4* const qk4 = reinterpret_cast<const uint4*>(g_QKb);
    const size_t rbase = (size_t)rr * NNODES;
    const uint32_t qsb[2] = { smem_u32(&Qs[0][0]), smem_u32(&Qs[1][0]) };
    const uint32_t ksb[2] = { smem_u32(&Ks[0][0]), smem_u32(&Ks[1][0]) };

    auto load_head = [&](int h, int b) {
        {
            const int row = tid >> 3, u4 = tid & 7;
            const int node = qn[row];
            if (node >= 0)
                cp_async16(qsb[b] + (row * LDK + u4 * 4) * 4,
                           qk4 + (rbase + node) * 128 + h * 8 + u4);
        }
#pragma unroll
        for (int it = 0; it < 3; it++) {
            const int idx = tid + it * 256;
            const int row = idx >> 3, u4 = idx & 7;
            const int node = kn[row];
            if (node >= 0)
                cp_async16(ksb[b] + (row * LDK + u4 * 4) * 4,
                           qk4 + (rbase + node) * 128 + 64 + h * 8 + u4);
        }
        asm volatile("cp.async.commit_group;" ::: "memory");
    };

    float acc[3][4];
#pragma unroll
    for (int j = 0; j < 3; j++)
#pragma unroll
        for (int i = 0; i < 4; i++) acc[j][i] = 0.f;

    load_head(hb, 0);

#pragma unroll 1
    for (int h4 = 0; h4 < 4; h4++) {
        const int b = h4 & 1;
        if (h4 < 3) {
            load_head(hb + h4 + 1, b ^ 1);
            asm volatile("cp.async.wait_group 1;" ::: "memory");
        } else {
            asm volatile("cp.async.wait_group 0;" ::: "memory");
        }
        __syncthreads();

        float c[3][4];
#pragma unroll
        for (int j = 0; j < 3; j++)
#pragma unroll
            for (int i = 0; i < 4; i++) c[j][i] = 0.f;

        const unsigned* Qb = &Qs[b][0];
        const unsigned* Kb = &Ks[b][0];
#pragma unroll
        for (int kb = 0; kb < 32; kb += 8) {
            unsigned a[4];
            const int ra = row0 * LDK + kb + tig;
            a[0] = Qb[ra];
            a[1] = Qb[ra + 8 * LDK];
            a[2] = Qb[ra + 4];
            a[3] = Qb[ra + 8 * LDK + 4];
#pragma unroll
            for (int j = 0; j < 3; j++) {
                const int rb = ((ntb + j) * 8 + grp) * LDK + kb + tig;
                mma_bf16(c[j], a, Kb[rb], Kb[rb + 4]);
            }
        }

        float e[3][4];
#pragma unroll
        for (int j = 0; j < 3; j++) {
            e[j][0] = __expf(c[j][0] * 0.125f) * mk[j][0];
            e[j][1] = __expf(c[j][1] * 0.125f) * mk[j][1];
            e[j][2] = __expf(c[j][2] * 0.125f) * mk[j][0];
            e[j][3] = __expf(c[j][3] * 0.125f) * mk[j][1];
        }

        float p0 = (e[0][0] + e[0][1]) + (e[1][0] + e[1][1]) + (e[2][0] + e[2][1]);
        float p1 = (e[0][2] + e[0][3]) + (e[1][2] + e[1][3]) + (e[2][2] + e[2][3]);
        p0 += __shfl_xor_sync(0xffffffffu, p0, 1);
        p0 += __shfl_xor_sync(0xffffffffu, p0, 2);
        p1 += __shfl_xor_sync(0xffffffffu, p1, 1);
        p1 += __shfl_xor_sync(0xffffffffu, p1, 2);
        if (tig == 0) {
            Ps[row0][nw] = p0;
            Ps[row1][nw] = p1;
        }
        __syncthreads();

        const float4 s0 = *reinterpret_cast<const float4*>(Ps[row0]);
        const float4 s1 = *reinterpret_cast<const float4*>(Ps[row1]);
        const float inv0 = __fdividef(1.f, (s0.x + s0.y) + (s0.z + s0.w));
        const float inv1 = __fdividef(1.f, (s1.x + s1.y) + (s1.z + s1.w));
#pragma unroll
        for (int j = 0; j < 3; j++) {
            acc[j][0] += e[j][0] * inv0;
            acc[j][1] += e[j][1] * inv0;
            acc[j][2] += e[j][2] * inv1;
            acc[j][3] += e[j][3] * inv1;
        }
    }

    const int q0 = qn[row0];
    const int q1 = qn[row1];
#pragma unroll
    for (int j = 0; j < 3; j++) {
        const int col = (ntb + j) * 8 + 2 * tig;
        const int k0 = kn[col], k1 = kn[col + 1];
        if (q0 >= 0) {
            float* rp = out + (size_t)q0 * RN + rbase;
            if (k0 >= 0) atomicAdd(rp + k0, acc[j][0] * 0.125f);
            if (k1 >= 0) atomicAdd(rp + k1, acc[j][1] * 0.125f);
        }
        if (q1 >= 0) {
            float* rp = out + (size_t)q1 * RN + rbase;
            if (k0 >= 0) atomicAdd(rp + k0, acc[j][2] * 0.125f);
            if (k1 >= 0) atomicAdd(rp + k1, acc[j][3] * 0.125f);
        }
    }
}

// ---------------------------------------------------------------------------
extern "C" void kernel_launch(void* const* d_in, const int* in_sizes, int n_in,
                              void* d_out, int out_size)
{
    const float* nf = (const float*)d_in[0];
    const float* Wq = (const float*)d_in[1];
    const float* bq = (const float*)d_in[2];
    const float* Wk = (const float*)d_in[3];
    const float* bk = (const float*)d_in[4];
    float* out = (float*)d_out;

    dim3 ggrid(8, (RN + 127) / 128);
    gemm_kernel<<<ggrid, 256>>>(nf, Wq, bq, Wk, bk, out);

    dim3 agrid(NWIN, RREL, 2);
    attn_kernel<<<agrid, 256>>>(out);
}